// round 1
// baseline (speedup 1.0000x reference)
#include <cuda_runtime.h>
#include <math.h>
#include <float.h>

// ---------------- scratch (device globals; no allocation allowed) ----------------
__device__ float g_h1[64 * 64 * 64 * 64];   // (64,64,64,64)
__device__ float g_a [64 * 128 * 32 * 32];  // (64,128,32,32)
__device__ float g_b [64 * 128 * 32 * 32];  // (64,128,32,32)
__device__ float g_m [64 * 64 * 32 * 32];   // (64,64,32,32)
__device__ float g_ze[64 * 64 * 32 * 32];   // (64,64,32,32)
__device__ float g_zq[64 * 64 * 32 * 32];   // (64,64,32,32)
__device__ float g_wt[972800];              // transposed weights, all layers
__device__ float g_En[512];
__device__ int   g_idx[65536];
__device__ int   g_cnt[512];
__device__ float g_sse;

// Transposed-weight offsets (floats), all 16B-aligned
#define OFF_ENC1     0        // 3*16*64     = 3072
#define OFF_ENC2     3072     // 64*16*128   = 131072
#define OFF_ENC3     134144   // 128*9*128   = 147456
#define OFF_ENC4     281600   // 147456
#define OFF_ERES1_0  429056   // 128*9*64    = 73728
#define OFF_ERES1_1  502784
#define OFF_ERES2_0  576512   // 64*1*128    = 8192
#define OFF_ERES2_1  584704
#define OFF_EADJ     592896   // 128*1*64    = 8192
#define OFF_DADJ     601088   // 64*9*128    = 73728
#define OFF_DRES1_0  674816
#define OFF_DRES1_1  748544
#define OFF_DRES2_0  822272
#define OFF_DRES2_1  830464
#define OFF_TC1      838656   // 128*16*64   = 131072
#define OFF_TC2      969728   // 64*16*3     = 3072

// ---------------- weight transform ----------------
// conv   (OIHW): wt[(ci*K2+kk)*COUT + co] = w[(co*CIN+ci)*K2 + kk]
// convT  (IOHW): wt[(ci*K2+kk)*COUT + co] = w[(ci*COUT+co)*K2 + kk]
__global__ void wtrans(const float* __restrict__ w, float* __restrict__ wt,
                       int CIN, int COUT, int K2, int transposed)
{
    int i = blockIdx.x * 256 + threadIdx.x;
    int total = CIN * COUT * K2;
    if (i >= total) return;
    int co = i % COUT;
    int t  = i / COUT;
    int kk = t % K2;
    int ci = t / K2;
    float v = transposed ? w[(ci * COUT + co) * K2 + kk]
                         : w[(co * CIN + ci) * K2 + kk];
    wt[i] = v;
}

// ---------------- generic tiled conv ----------------
// Block: 8 rows x 16 cols output pixels x 64 output channels, 256 threads.
// Thread: 4 oc x 8 px register tile.
template<int CIN, int COUT, int KS, int S, int P, int CICH,
         bool RELU_IN, bool HAS_BIAS, bool RELU_OUT, bool ADD_RES>
__global__ __launch_bounds__(256)
void conv_tiled(const float* __restrict__ in, const float* __restrict__ wt,
                const float* __restrict__ bias, const float* __restrict__ res,
                float* __restrict__ out, int H, int W, int OH, int OW, int TX)
{
    constexpr int ITH = 7 * S + KS;
    constexpr int ITW = 15 * S + KS;
    __shared__ float sm[CICH * ITH * ITW];

    const int tile = blockIdx.x;
    const int tx = tile % TX, ty = tile / TX;
    const int ocb = blockIdx.y, n = blockIdx.z;
    const int tid = threadIdx.x;
    const int ocl = (tid & 15) << 2;
    const int pg = tid >> 4;
    const int r = pg >> 1, ch = pg & 1;
    const int oc = (ocb << 6) + ocl;

    float acc[4][8];
#pragma unroll
    for (int o = 0; o < 4; o++)
#pragma unroll
        for (int p = 0; p < 8; p++) acc[o][p] = 0.f;

    const int iy0 = ty * 8 * S - P;
    const int ix0 = tx * 16 * S - P;
    const float* inb = in + (long)n * CIN * H * W;

    for (int cc = 0; cc < CIN; cc += CICH) {
        for (int i = tid; i < CICH * ITH * ITW; i += 256) {
            int ci = i / (ITH * ITW);
            int rem = i - ci * (ITH * ITW);
            int iy = rem / ITW, ix = rem - iy * ITW;
            int gy = iy0 + iy, gx = ix0 + ix;
            float v = 0.f;
            if ((unsigned)gy < (unsigned)H && (unsigned)gx < (unsigned)W)
                v = inb[(cc + ci) * H * W + gy * W + gx];
            if (RELU_IN) v = fmaxf(v, 0.f);
            sm[i] = v;
        }
        __syncthreads();
#pragma unroll 1
        for (int ci = 0; ci < CICH; ci++) {
            const float* sp = sm + ci * ITH * ITW + (r * S) * ITW + (ch * 8) * S;
            const float* wp = wt + (long)((cc + ci) * KS * KS) * COUT + oc;
#pragma unroll
            for (int ky = 0; ky < KS; ky++) {
#pragma unroll
                for (int kx = 0; kx < KS; kx++) {
                    float4 w4 = *(const float4*)(wp + (ky * KS + kx) * COUT);
                    const float* sr = sp + ky * ITW + kx;
#pragma unroll
                    for (int px = 0; px < 8; px++) {
                        float xv = sr[px * S];
                        acc[0][px] = fmaf(w4.x, xv, acc[0][px]);
                        acc[1][px] = fmaf(w4.y, xv, acc[1][px]);
                        acc[2][px] = fmaf(w4.z, xv, acc[2][px]);
                        acc[3][px] = fmaf(w4.w, xv, acc[3][px]);
                    }
                }
            }
        }
        __syncthreads();
    }

    float bv[4] = {0.f, 0.f, 0.f, 0.f};
    if (HAS_BIAS) {
        float4 b4 = *(const float4*)(bias + oc);
        bv[0] = b4.x; bv[1] = b4.y; bv[2] = b4.z; bv[3] = b4.w;
    }
    const int oy = ty * 8 + r;
    const int oxb = tx * 16 + ch * 8;
#pragma unroll
    for (int o = 0; o < 4; o++) {
        long base = ((long)(n * COUT + oc + o) * OH + oy) * OW + oxb;
#pragma unroll
        for (int px = 0; px < 8; px++) {
            float v = acc[o][px] + bv[o];
            if (ADD_RES) v += res[base + px];
            if (RELU_OUT) v = fmaxf(v, 0.f);
            out[base + px] = v;
        }
    }
}

// ---------------- tiled conv-transpose (k=4, s=2, p=1) ----------------
// For output index o: taps j in {0,1}: i_j = ((o+1)>>1) - j, k_j = (1-(o&1)) + 2j.
template<int CIN, int COUT, bool RELU_IN, bool RELU_OUT>
__global__ __launch_bounds__(256)
void convt_tiled(const float* __restrict__ in, const float* __restrict__ wt,
                 const float* __restrict__ bias, float* __restrict__ out,
                 int IH, int IW, int OH, int OW, int TX)
{
    constexpr int CICH = 8;
    constexpr int STH = 6, STW = 10;
    __shared__ float sm[CICH * STH * STW];

    const int tile = blockIdx.x;
    const int tx = tile % TX, ty = tile / TX;
    const int ocb = blockIdx.y, n = blockIdx.z;
    const int tid = threadIdx.x;
    const int ocl = (tid & 15) << 2;
    const int pg = tid >> 4;
    const int r = pg >> 1, ch = pg & 1;
    const int oc = (ocb << 6) + ocl;

    float acc[4][8];
#pragma unroll
    for (int o = 0; o < 4; o++)
#pragma unroll
        for (int p = 0; p < 8; p++) acc[o][p] = 0.f;

    const int iyb = ty * 4 - 1;
    const int ixb = tx * 8 - 1;
    const float* inb = in + (long)n * CIN * IH * IW;
    const int oy = ty * 8 + r;
    const int pe = oy & 1;

    for (int cc = 0; cc < CIN; cc += CICH) {
        for (int i = tid; i < CICH * STH * STW; i += 256) {
            int ci = i / (STH * STW);
            int rem = i - ci * (STH * STW);
            int iy = rem / STW, ix = rem - iy * STW;
            int gy = iyb + iy, gx = ixb + ix;
            float v = 0.f;
            if ((unsigned)gy < (unsigned)IH && (unsigned)gx < (unsigned)IW)
                v = inb[(cc + ci) * IH * IW + gy * IW + gx];
            if (RELU_IN) v = fmaxf(v, 0.f);
            sm[i] = v;
        }
        __syncthreads();
#pragma unroll 1
        for (int ci = 0; ci < CICH; ci++) {
#pragma unroll
            for (int jy = 0; jy < 2; jy++) {
                int ly = ((oy + 1) >> 1) - jy - iyb;
                int ky = (1 - pe) + 2 * jy;
#pragma unroll
                for (int jx = 0; jx < 2; jx++) {
                    const float* sp = sm + ci * STH * STW + ly * STW + (ch * 4 + 1 - jx);
                    float4 wa = *(const float4*)(wt + (long)((cc + ci) * 16 + ky * 4 + (1 + 2 * jx)) * COUT + oc); // even ox
                    float4 wb = *(const float4*)(wt + (long)((cc + ci) * 16 + ky * 4 + (2 * jx)) * COUT + oc);     // odd ox
#pragma unroll
                    for (int px = 0; px < 8; px++) {
                        float xv = sp[(px + 1) >> 1];
                        float4 w4 = (px & 1) ? wb : wa;
                        acc[0][px] = fmaf(w4.x, xv, acc[0][px]);
                        acc[1][px] = fmaf(w4.y, xv, acc[1][px]);
                        acc[2][px] = fmaf(w4.z, xv, acc[2][px]);
                        acc[3][px] = fmaf(w4.w, xv, acc[3][px]);
                    }
                }
            }
        }
        __syncthreads();
    }

    float4 b4 = *(const float4*)(bias + oc);
    float bv[4] = {b4.x, b4.y, b4.z, b4.w};
    const int oxb = tx * 16 + ch * 8;
#pragma unroll
    for (int o = 0; o < 4; o++) {
        long base = ((long)(n * COUT + oc + o) * OH + oy) * OW + oxb;
#pragma unroll
        for (int px = 0; px < 8; px++) {
            float v = acc[o][px] + bv[o];
            if (RELU_OUT) v = fmaxf(v, 0.f);
            out[base + px] = v;
        }
    }
}

// ---------------- conv-transpose to 3 channels (final recon) ----------------
__global__ __launch_bounds__(256)
void convt_c3(const float* __restrict__ in, const float* __restrict__ wt,
              const float* __restrict__ bias, float* __restrict__ out)
{
    // in: (64,64,64,64) -> out: (64,3,128,128). Tile 8x32, one px per thread.
    __shared__ float swt[64 * 16 * 3];
    __shared__ float sin_[8 * 6 * 18];
    const int tile = blockIdx.x;              // TX=4 (32-col tiles), TY=16
    const int tx = tile & 3, ty = tile >> 2;
    const int n = blockIdx.z;
    const int tid = threadIdx.x;
    for (int i = tid; i < 3072; i += 256) swt[i] = wt[i];

    const int r = tid >> 5, c = tid & 31;
    const int oy = ty * 8 + r, ox = tx * 32 + c;
    const int iyb = ty * 4 - 1, ixb = tx * 16 - 1;
    const int pey = oy & 1, pex = ox & 1;
    float a0 = 0.f, a1 = 0.f, a2 = 0.f;
    const float* inb = in + (long)n * 64 * 64 * 64;

    for (int cc = 0; cc < 64; cc += 8) {
        __syncthreads();
        for (int i = tid; i < 8 * 6 * 18; i += 256) {
            int ci = i / 108;
            int rem = i - ci * 108;
            int iy = rem / 18, ix = rem - iy * 18;
            int gy = iyb + iy, gx = ixb + ix;
            float v = 0.f;
            if ((unsigned)gy < 64u && (unsigned)gx < 64u)
                v = inb[(cc + ci) * 4096 + gy * 64 + gx];
            sin_[i] = v;
        }
        __syncthreads();
#pragma unroll 1
        for (int ci = 0; ci < 8; ci++) {
#pragma unroll
            for (int jy = 0; jy < 2; jy++) {
                int ly = ((oy + 1) >> 1) - jy - iyb;
                int ky = (1 - pey) + 2 * jy;
#pragma unroll
                for (int jx = 0; jx < 2; jx++) {
                    int lx = ((ox + 1) >> 1) - jx - ixb;
                    int kx = (1 - pex) + 2 * jx;
                    float xv = sin_[ci * 108 + ly * 18 + lx];
                    const float* w = swt + ((cc + ci) * 16 + ky * 4 + kx) * 3;
                    a0 = fmaf(xv, w[0], a0);
                    a1 = fmaf(xv, w[1], a1);
                    a2 = fmaf(xv, w[2], a2);
                }
            }
        }
    }
    long base = (long)n * 3 * 128 * 128 + oy * 128 + ox;
    out[base]             = a0 + bias[0];
    out[base + 16384]     = a1 + bias[1];
    out[base + 32768]     = a2 + bias[2];
}

// ---------------- VQ ----------------
__global__ void vq_en(const float* __restrict__ E)
{
    int k = blockIdx.x * 128 + threadIdx.x;
    if (k < 512) {
        float s = 0.f;
#pragma unroll
        for (int d = 0; d < 64; d++) { float e = E[k * 64 + d]; s = fmaf(e, e, s); }
        g_En[k] = s;
    }
}

__global__ __launch_bounds__(256)
void vq_argmin(const float* __restrict__ ze, const float* __restrict__ E)
{
    __shared__ float se[64 * 64];
    __shared__ float sen[64];
    const int tid = threadIdx.x;
    const int p = blockIdx.x * 256 + tid;
    const int b = p >> 10, s = p & 1023;
    const float* zp = ze + (long)b * 65536 + s;
    float z[64];
#pragma unroll
    for (int d = 0; d < 64; d++) z[d] = zp[d * 1024];
    float best = FLT_MAX;
    int bi = 0;
    for (int c0 = 0; c0 < 512; c0 += 64) {
        __syncthreads();
        for (int i = tid; i < 4096; i += 256) se[i] = E[c0 * 64 + i];
        if (tid < 64) sen[tid] = g_En[c0 + tid];
        __syncthreads();
        for (int k = 0; k < 64; k++) {
            const float4* ep = (const float4*)(se + k * 64);
            float dot = 0.f;
#pragma unroll
            for (int q = 0; q < 16; q++) {
                float4 e4 = ep[q];
                dot = fmaf(z[4 * q + 0], e4.x, dot);
                dot = fmaf(z[4 * q + 1], e4.y, dot);
                dot = fmaf(z[4 * q + 2], e4.z, dot);
                dot = fmaf(z[4 * q + 3], e4.w, dot);
            }
            float dist = sen[k] - 2.f * dot;
            if (dist < best) { best = dist; bi = c0 + k; }
        }
    }
    g_idx[p] = bi;
}

__global__ __launch_bounds__(256)
void vq_loss(const float* __restrict__ ze, const float* __restrict__ E,
             float* __restrict__ zq)
{
    __shared__ int h[512];
    __shared__ float red[8];
    const int tid = threadIdx.x;
    for (int i = tid; i < 512; i += 256) h[i] = 0;
    __syncthreads();
    const int p = blockIdx.x * 256 + tid;
    const int b = p >> 10, s = p & 1023;
    const int id = g_idx[p];
    atomicAdd(&h[id], 1);
    const float* ep = E + id * 64;
    const float* zp = ze + (long)b * 65536 + s;
    float* qp = zq + (long)b * 65536 + s;
    float sse = 0.f;
#pragma unroll
    for (int d = 0; d < 64; d++) {
        float e = ep[d];
        float diff = e - zp[d * 1024];
        sse = fmaf(diff, diff, sse);
        qp[d * 1024] = e;
    }
#pragma unroll
    for (int off = 16; off; off >>= 1) sse += __shfl_down_sync(0xffffffffu, sse, off);
    if ((tid & 31) == 0) red[tid >> 5] = sse;
    __syncthreads();
    for (int i = tid; i < 512; i += 256)
        if (h[i]) atomicAdd(&g_cnt[i], h[i]);
    if (tid == 0) {
        float t = 0.f;
#pragma unroll
        for (int w = 0; w < 8; w++) t += red[w];
        atomicAdd(&g_sse, t);
    }
}

__global__ void clear_k()
{
    int t = threadIdx.x;
    if (t < 512) g_cnt[t] = 0;
    if (t == 0) g_sse = 0.f;
}

__global__ void finalize(float* __restrict__ out)
{
    __shared__ float red[512];
    int t = threadIdx.x;
    float cnt = (float)g_cnt[t];
    float pr = cnt * (1.f / 65536.f);
    red[t] = (cnt > 0.f) ? (-pr * log2f(pr + 1e-10f)) : 0.f;
    __syncthreads();
    for (int o = 256; o; o >>= 1) {
        if (t < o) red[t] += red[t + o];
        __syncthreads();
    }
    if (t == 0) {
        float ent = red[0];
        float mse = g_sse / (65536.f * 64.f);
        out[0] = 1.25f * mse;                 // e_and_q = q + 0.25*e
        out[1 + 3145728] = mse;               // e_latent_loss
        out[2 + 3145728] = mse;               // q_latent_loss
        out[3 + 3145728] = exp2f(ent);        // est_words
    }
}

// ---------------- host ----------------
extern "C" void kernel_launch(void* const* d_in, const int* in_sizes, int n_in,
                              void* d_out, int out_size)
{
    (void)in_sizes; (void)n_in; (void)out_size;
    const float* x        = (const float*)d_in[0];
    const float* enc_w1   = (const float*)d_in[1];
    const float* enc_b1   = (const float*)d_in[2];
    const float* enc_w2   = (const float*)d_in[3];
    const float* enc_b2   = (const float*)d_in[4];
    const float* enc_w3   = (const float*)d_in[5];
    const float* enc_b3   = (const float*)d_in[6];
    const float* enc_w4   = (const float*)d_in[7];
    const float* enc_b4   = (const float*)d_in[8];
    const float* eres_w1  = (const float*)d_in[9];
    const float* eres_w2  = (const float*)d_in[10];
    const float* eadj_w   = (const float*)d_in[11];
    const float* eadj_b   = (const float*)d_in[12];
    const float* E        = (const float*)d_in[13];
    const float* dadj_w   = (const float*)d_in[14];
    const float* dadj_b   = (const float*)d_in[15];
    const float* dres_w1  = (const float*)d_in[16];
    const float* dres_w2  = (const float*)d_in[17];
    const float* tc1_w    = (const float*)d_in[18];
    const float* tc1_b    = (const float*)d_in[19];
    const float* tc2_w    = (const float*)d_in[20];
    const float* tc2_b    = (const float*)d_in[21];

    float *h1, *a, *bb, *m, *ze, *zq, *wt;
    cudaGetSymbolAddress((void**)&h1, g_h1);
    cudaGetSymbolAddress((void**)&a,  g_a);
    cudaGetSymbolAddress((void**)&bb, g_b);
    cudaGetSymbolAddress((void**)&m,  g_m);
    cudaGetSymbolAddress((void**)&ze, g_ze);
    cudaGetSymbolAddress((void**)&zq, g_zq);
    cudaGetSymbolAddress((void**)&wt, g_wt);

    // weight transforms (tiny)
    auto T = [&](const float* w, float* dst, int CIN, int COUT, int K2, int tr) {
        int total = CIN * COUT * K2;
        wtrans<<<(total + 255) / 256, 256>>>(w, dst, CIN, COUT, K2, tr);
    };
    T(enc_w1,           wt + OFF_ENC1,    3,   64,  16, 0);
    T(enc_w2,           wt + OFF_ENC2,    64,  128, 16, 0);
    T(enc_w3,           wt + OFF_ENC3,    128, 128, 9,  0);
    T(enc_w4,           wt + OFF_ENC4,    128, 128, 9,  0);
    T(eres_w1,          wt + OFF_ERES1_0, 128, 64,  9,  0);
    T(eres_w1 + 73728,  wt + OFF_ERES1_1, 128, 64,  9,  0);
    T(eres_w2,          wt + OFF_ERES2_0, 64,  128, 1,  0);
    T(eres_w2 + 8192,   wt + OFF_ERES2_1, 64,  128, 1,  0);
    T(eadj_w,           wt + OFF_EADJ,    128, 64,  1,  0);
    T(dadj_w,           wt + OFF_DADJ,    64,  128, 9,  0);
    T(dres_w1,          wt + OFF_DRES1_0, 128, 64,  9,  0);
    T(dres_w1 + 73728,  wt + OFF_DRES1_1, 128, 64,  9,  0);
    T(dres_w2,          wt + OFF_DRES2_0, 64,  128, 1,  0);
    T(dres_w2 + 8192,   wt + OFF_DRES2_1, 64,  128, 1,  0);
    T(tc1_w,            wt + OFF_TC1,     128, 64,  16, 1);
    T(tc2_w,            wt + OFF_TC2,     64,  3,   16, 1);

    clear_k<<<1, 512>>>();
    vq_en<<<4, 128>>>(E);

    // ---- encoder ----
    conv_tiled<3, 64, 4, 2, 1, 3, false, true, true, false>
        <<<dim3(32, 1, 64), 256>>>(x, wt + OFF_ENC1, enc_b1, nullptr, h1, 128, 128, 64, 64, 4);
    conv_tiled<64, 128, 4, 2, 1, 8, false, true, true, false>
        <<<dim3(8, 2, 64), 256>>>(h1, wt + OFF_ENC2, enc_b2, nullptr, a, 64, 64, 32, 32, 2);
    conv_tiled<128, 128, 3, 1, 1, 8, false, true, true, false>
        <<<dim3(8, 2, 64), 256>>>(a, wt + OFF_ENC3, enc_b3, nullptr, bb, 32, 32, 32, 32, 2);
    conv_tiled<128, 128, 3, 1, 1, 8, false, true, false, false>
        <<<dim3(8, 2, 64), 256>>>(bb, wt + OFF_ENC4, enc_b4, nullptr, a, 32, 32, 32, 32, 2);
    // enc res block 0
    conv_tiled<128, 64, 3, 1, 1, 8, true, false, false, false>
        <<<dim3(8, 1, 64), 256>>>(a, wt + OFF_ERES1_0, nullptr, nullptr, m, 32, 32, 32, 32, 2);
    conv_tiled<64, 128, 1, 1, 0, 8, true, false, false, true>
        <<<dim3(8, 2, 64), 256>>>(m, wt + OFF_ERES2_0, nullptr, a, a, 32, 32, 32, 32, 2);
    // enc res block 1
    conv_tiled<128, 64, 3, 1, 1, 8, true, false, false, false>
        <<<dim3(8, 1, 64), 256>>>(a, wt + OFF_ERES1_1, nullptr, nullptr, m, 32, 32, 32, 32, 2);
    conv_tiled<64, 128, 1, 1, 0, 8, true, false, false, true>
        <<<dim3(8, 2, 64), 256>>>(m, wt + OFF_ERES2_1, nullptr, a, a, 32, 32, 32, 32, 2);
    // enc_adj consumes relu(res_stack output)
    conv_tiled<128, 64, 1, 1, 0, 8, true, true, false, false>
        <<<dim3(8, 1, 64), 256>>>(a, wt + OFF_EADJ, eadj_b, nullptr, ze, 32, 32, 32, 32, 2);

    // ---- vector quantizer ----
    vq_argmin<<<256, 256>>>(ze, E);
    vq_loss<<<256, 256>>>(ze, E, zq);

    // ---- decoder ----
    conv_tiled<64, 128, 3, 1, 1, 8, false, true, false, false>
        <<<dim3(8, 2, 64), 256>>>(zq, wt + OFF_DADJ, dadj_b, nullptr, a, 32, 32, 32, 32, 2);
    // dec res block 0
    conv_tiled<128, 64, 3, 1, 1, 8, true, false, false, false>
        <<<dim3(8, 1, 64), 256>>>(a, wt + OFF_DRES1_0, nullptr, nullptr, m, 32, 32, 32, 32, 2);
    conv_tiled<64, 128, 1, 1, 0, 8, true, false, false, true>
        <<<dim3(8, 2, 64), 256>>>(m, wt + OFF_DRES2_0, nullptr, a, a, 32, 32, 32, 32, 2);
    // dec res block 1
    conv_tiled<128, 64, 3, 1, 1, 8, true, false, false, false>
        <<<dim3(8, 1, 64), 256>>>(a, wt + OFF_DRES1_1, nullptr, nullptr, m, 32, 32, 32, 32, 2);
    conv_tiled<64, 128, 1, 1, 0, 8, true, false, false, true>
        <<<dim3(8, 2, 64), 256>>>(m, wt + OFF_DRES2_1, nullptr, a, a, 32, 32, 32, 32, 2);
    // tc1 consumes relu(res_stack output)
    convt_tiled<128, 64, true, true>
        <<<dim3(32, 1, 64), 256>>>(a, wt + OFF_TC1, tc1_b, h1, 32, 32, 64, 64, 4);
    // tc2 -> x_recon straight into d_out (offset 1)
    convt_c3<<<dim3(64, 1, 64), 256>>>(h1, wt + OFF_TC2, tc2_b, (float*)d_out + 1);

    finalize<<<1, 512>>>((float*)d_out);
}

// round 2
// speedup vs baseline: 1.0031x; 1.0031x over previous
#include <cuda_runtime.h>
#include <math.h>
#include <float.h>

// ---------------- scratch (device globals; no allocation allowed) ----------------
__device__ float g_h1[64 * 64 * 64 * 64];   // (64,64,64,64)
__device__ float g_a [64 * 128 * 32 * 32];  // (64,128,32,32)
__device__ float g_b [64 * 128 * 32 * 32];  // (64,128,32,32)
__device__ float g_m [64 * 64 * 32 * 32];   // (64,64,32,32)
__device__ float g_ze[64 * 64 * 32 * 32];   // (64,64,32,32)
__device__ float g_zq[64 * 64 * 32 * 32];   // (64,64,32,32)
__device__ float g_wt[972800];              // transposed weights, all layers
__device__ float g_En[512];
__device__ int   g_idx[65536];
__device__ int   g_cnt[512];
__device__ float g_sse;

// Transposed-weight offsets (floats), all 16B-aligned
#define OFF_ENC1     0        // 3*16*64     = 3072
#define OFF_ENC2     3072     // 64*16*128   = 131072
#define OFF_ENC3     134144   // 128*9*128   = 147456
#define OFF_ENC4     281600   // 147456
#define OFF_ERES1_0  429056   // 128*9*64    = 73728
#define OFF_ERES1_1  502784
#define OFF_ERES2_0  576512   // 64*1*128    = 8192
#define OFF_ERES2_1  584704
#define OFF_EADJ     592896   // 128*1*64    = 8192
#define OFF_DADJ     601088   // 64*9*128    = 73728
#define OFF_DRES1_0  674816
#define OFF_DRES1_1  748544
#define OFF_DRES2_0  822272
#define OFF_DRES2_1  830464
#define OFF_TC1      838656   // 128*16*64   = 131072
#define OFF_TC2      969728   // 64*16*3     = 3072

// ---------------- weight transform ----------------
// conv   (OIHW): wt[(ci*K2+kk)*COUT + co] = w[(co*CIN+ci)*K2 + kk]
// convT  (IOHW): wt[(ci*K2+kk)*COUT + co] = w[(ci*COUT+co)*K2 + kk]
__global__ void wtrans(const float* __restrict__ w, float* __restrict__ wt,
                       int CIN, int COUT, int K2, int transposed)
{
    int i = blockIdx.x * 256 + threadIdx.x;
    int total = CIN * COUT * K2;
    if (i >= total) return;
    int co = i % COUT;
    int t  = i / COUT;
    int kk = t % K2;
    int ci = t / K2;
    float v = transposed ? w[(ci * COUT + co) * K2 + kk]
                         : w[(co * CIN + ci) * K2 + kk];
    wt[i] = v;
}

// ---------------- generic tiled conv ----------------
// Block: 8 rows x 16 cols output pixels x 64 output channels, 256 threads.
// Thread: 4 oc x 8 px register tile.
template<int CIN, int COUT, int KS, int S, int P, int CICH,
         bool RELU_IN, bool HAS_BIAS, bool RELU_OUT, bool ADD_RES>
__global__ __launch_bounds__(256)
void conv_tiled(const float* __restrict__ in, const float* __restrict__ wt,
                const float* __restrict__ bias, const float* __restrict__ res,
                float* __restrict__ out, int H, int W, int OH, int OW, int TX)
{
    constexpr int ITH = 7 * S + KS;
    constexpr int ITW = 15 * S + KS;
    __shared__ float sm[CICH * ITH * ITW];

    const int tile = blockIdx.x;
    const int tx = tile % TX, ty = tile / TX;
    const int ocb = blockIdx.y, n = blockIdx.z;
    const int tid = threadIdx.x;
    const int ocl = (tid & 15) << 2;
    const int pg = tid >> 4;
    const int r = pg >> 1, ch = pg & 1;
    const int oc = (ocb << 6) + ocl;

    float acc[4][8];
#pragma unroll
    for (int o = 0; o < 4; o++)
#pragma unroll
        for (int p = 0; p < 8; p++) acc[o][p] = 0.f;

    const int iy0 = ty * 8 * S - P;
    const int ix0 = tx * 16 * S - P;
    const float* inb = in + (long)n * CIN * H * W;

    for (int cc = 0; cc < CIN; cc += CICH) {
        for (int i = tid; i < CICH * ITH * ITW; i += 256) {
            int ci = i / (ITH * ITW);
            int rem = i - ci * (ITH * ITW);
            int iy = rem / ITW, ix = rem - iy * ITW;
            int gy = iy0 + iy, gx = ix0 + ix;
            float v = 0.f;
            if ((unsigned)gy < (unsigned)H && (unsigned)gx < (unsigned)W)
                v = inb[(cc + ci) * H * W + gy * W + gx];
            if (RELU_IN) v = fmaxf(v, 0.f);
            sm[i] = v;
        }
        __syncthreads();
#pragma unroll 1
        for (int ci = 0; ci < CICH; ci++) {
            const float* sp = sm + ci * ITH * ITW + (r * S) * ITW + (ch * 8) * S;
            const float* wp = wt + (long)((cc + ci) * KS * KS) * COUT + oc;
#pragma unroll
            for (int ky = 0; ky < KS; ky++) {
#pragma unroll
                for (int kx = 0; kx < KS; kx++) {
                    float4 w4 = *(const float4*)(wp + (ky * KS + kx) * COUT);
                    const float* sr = sp + ky * ITW + kx;
#pragma unroll
                    for (int px = 0; px < 8; px++) {
                        float xv = sr[px * S];
                        acc[0][px] = fmaf(w4.x, xv, acc[0][px]);
                        acc[1][px] = fmaf(w4.y, xv, acc[1][px]);
                        acc[2][px] = fmaf(w4.z, xv, acc[2][px]);
                        acc[3][px] = fmaf(w4.w, xv, acc[3][px]);
                    }
                }
            }
        }
        __syncthreads();
    }

    float bv[4] = {0.f, 0.f, 0.f, 0.f};
    if (HAS_BIAS) {
        float4 b4 = *(const float4*)(bias + oc);
        bv[0] = b4.x; bv[1] = b4.y; bv[2] = b4.z; bv[3] = b4.w;
    }
    const int oy = ty * 8 + r;
    const int oxb = tx * 16 + ch * 8;
#pragma unroll
    for (int o = 0; o < 4; o++) {
        long base = ((long)(n * COUT + oc + o) * OH + oy) * OW + oxb;
#pragma unroll
        for (int px = 0; px < 8; px++) {
            float v = acc[o][px] + bv[o];
            if (ADD_RES) v += res[base + px];
            if (RELU_OUT) v = fmaxf(v, 0.f);
            out[base + px] = v;
        }
    }
}

// ---------------- tiled conv-transpose (k=4, s=2, p=1) ----------------
// For output index o: taps j in {0,1}: i_j = ((o+1)>>1) - j, k_j = (1-(o&1)) + 2j.
template<int CIN, int COUT, bool RELU_IN, bool RELU_OUT>
__global__ __launch_bounds__(256)
void convt_tiled(const float* __restrict__ in, const float* __restrict__ wt,
                 const float* __restrict__ bias, float* __restrict__ out,
                 int IH, int IW, int OH, int OW, int TX)
{
    constexpr int CICH = 8;
    constexpr int STH = 6, STW = 10;
    __shared__ float sm[CICH * STH * STW];

    const int tile = blockIdx.x;
    const int tx = tile % TX, ty = tile / TX;
    const int ocb = blockIdx.y, n = blockIdx.z;
    const int tid = threadIdx.x;
    const int ocl = (tid & 15) << 2;
    const int pg = tid >> 4;
    const int r = pg >> 1, ch = pg & 1;
    const int oc = (ocb << 6) + ocl;

    float acc[4][8];
#pragma unroll
    for (int o = 0; o < 4; o++)
#pragma unroll
        for (int p = 0; p < 8; p++) acc[o][p] = 0.f;

    const int iyb = ty * 4 - 1;
    const int ixb = tx * 8 - 1;
    const float* inb = in + (long)n * CIN * IH * IW;
    const int oy = ty * 8 + r;
    const int pe = oy & 1;

    for (int cc = 0; cc < CIN; cc += CICH) {
        for (int i = tid; i < CICH * STH * STW; i += 256) {
            int ci = i / (STH * STW);
            int rem = i - ci * (STH * STW);
            int iy = rem / STW, ix = rem - iy * STW;
            int gy = iyb + iy, gx = ixb + ix;
            float v = 0.f;
            if ((unsigned)gy < (unsigned)IH && (unsigned)gx < (unsigned)IW)
                v = inb[(cc + ci) * IH * IW + gy * IW + gx];
            if (RELU_IN) v = fmaxf(v, 0.f);
            sm[i] = v;
        }
        __syncthreads();
#pragma unroll 1
        for (int ci = 0; ci < CICH; ci++) {
#pragma unroll
            for (int jy = 0; jy < 2; jy++) {
                int ly = ((oy + 1) >> 1) - jy - iyb;
                int ky = (1 - pe) + 2 * jy;
#pragma unroll
                for (int jx = 0; jx < 2; jx++) {
                    const float* sp = sm + ci * STH * STW + ly * STW + (ch * 4 + 1 - jx);
                    float4 wa = *(const float4*)(wt + (long)((cc + ci) * 16 + ky * 4 + (1 + 2 * jx)) * COUT + oc); // even ox
                    float4 wb = *(const float4*)(wt + (long)((cc + ci) * 16 + ky * 4 + (2 * jx)) * COUT + oc);     // odd ox
#pragma unroll
                    for (int px = 0; px < 8; px++) {
                        float xv = sp[(px + 1) >> 1];
                        float4 w4 = (px & 1) ? wb : wa;
                        acc[0][px] = fmaf(w4.x, xv, acc[0][px]);
                        acc[1][px] = fmaf(w4.y, xv, acc[1][px]);
                        acc[2][px] = fmaf(w4.z, xv, acc[2][px]);
                        acc[3][px] = fmaf(w4.w, xv, acc[3][px]);
                    }
                }
            }
        }
        __syncthreads();
    }

    float4 b4 = *(const float4*)(bias + oc);
    float bv[4] = {b4.x, b4.y, b4.z, b4.w};
    const int oxb = tx * 16 + ch * 8;
#pragma unroll
    for (int o = 0; o < 4; o++) {
        long base = ((long)(n * COUT + oc + o) * OH + oy) * OW + oxb;
#pragma unroll
        for (int px = 0; px < 8; px++) {
            float v = acc[o][px] + bv[o];
            if (RELU_OUT) v = fmaxf(v, 0.f);
            out[base + px] = v;
        }
    }
}

// ---------------- conv-transpose to 3 channels (final recon) ----------------
__global__ __launch_bounds__(256)
void convt_c3(const float* __restrict__ in, const float* __restrict__ wt,
              const float* __restrict__ bias, float* __restrict__ out)
{
    // in: (64,64,64,64) -> out: (64,3,128,128). Tile 8x32, one px per thread.
    __shared__ float swt[64 * 16 * 3];
    __shared__ float sin_[8 * 6 * 18];
    const int tile = blockIdx.x;              // TX=4 (32-col tiles), TY=16
    const int tx = tile & 3, ty = tile >> 2;
    const int n = blockIdx.z;
    const int tid = threadIdx.x;
    for (int i = tid; i < 3072; i += 256) swt[i] = wt[i];

    const int r = tid >> 5, c = tid & 31;
    const int oy = ty * 8 + r, ox = tx * 32 + c;
    const int iyb = ty * 4 - 1, ixb = tx * 16 - 1;
    const int pey = oy & 1, pex = ox & 1;
    float a0 = 0.f, a1 = 0.f, a2 = 0.f;
    const float* inb = in + (long)n * 64 * 64 * 64;

    for (int cc = 0; cc < 64; cc += 8) {
        __syncthreads();
        for (int i = tid; i < 8 * 6 * 18; i += 256) {
            int ci = i / 108;
            int rem = i - ci * 108;
            int iy = rem / 18, ix = rem - iy * 18;
            int gy = iyb + iy, gx = ixb + ix;
            float v = 0.f;
            if ((unsigned)gy < 64u && (unsigned)gx < 64u)
                v = inb[(cc + ci) * 4096 + gy * 64 + gx];
            sin_[i] = v;
        }
        __syncthreads();
#pragma unroll 1
        for (int ci = 0; ci < 8; ci++) {
#pragma unroll
            for (int jy = 0; jy < 2; jy++) {
                int ly = ((oy + 1) >> 1) - jy - iyb;
                int ky = (1 - pey) + 2 * jy;
#pragma unroll
                for (int jx = 0; jx < 2; jx++) {
                    int lx = ((ox + 1) >> 1) - jx - ixb;
                    int kx = (1 - pex) + 2 * jx;
                    float xv = sin_[ci * 108 + ly * 18 + lx];
                    const float* w = swt + ((cc + ci) * 16 + ky * 4 + kx) * 3;
                    a0 = fmaf(xv, w[0], a0);
                    a1 = fmaf(xv, w[1], a1);
                    a2 = fmaf(xv, w[2], a2);
                }
            }
        }
    }
    long base = (long)n * 3 * 128 * 128 + oy * 128 + ox;
    out[base]             = a0 + bias[0];
    out[base + 16384]     = a1 + bias[1];
    out[base + 32768]     = a2 + bias[2];
}

// ---------------- VQ ----------------
__global__ void vq_en(const float* __restrict__ E)
{
    int k = blockIdx.x * 128 + threadIdx.x;
    if (k < 512) {
        float s = 0.f;
#pragma unroll
        for (int d = 0; d < 64; d++) { float e = E[k * 64 + d]; s = fmaf(e, e, s); }
        g_En[k] = s;
    }
}

__global__ __launch_bounds__(256)
void vq_argmin(const float* __restrict__ ze, const float* __restrict__ E)
{
    __shared__ float se[64 * 64];
    __shared__ float sen[64];
    const int tid = threadIdx.x;
    const int p = blockIdx.x * 256 + tid;
    const int b = p >> 10, s = p & 1023;
    const float* zp = ze + (long)b * 65536 + s;
    float z[64];
#pragma unroll
    for (int d = 0; d < 64; d++) z[d] = zp[d * 1024];
    float best = FLT_MAX;
    int bi = 0;
    for (int c0 = 0; c0 < 512; c0 += 64) {
        __syncthreads();
        for (int i = tid; i < 4096; i += 256) se[i] = E[c0 * 64 + i];
        if (tid < 64) sen[tid] = g_En[c0 + tid];
        __syncthreads();
        for (int k = 0; k < 64; k++) {
            const float4* ep = (const float4*)(se + k * 64);
            float dot = 0.f;
#pragma unroll
            for (int q = 0; q < 16; q++) {
                float4 e4 = ep[q];
                dot = fmaf(z[4 * q + 0], e4.x, dot);
                dot = fmaf(z[4 * q + 1], e4.y, dot);
                dot = fmaf(z[4 * q + 2], e4.z, dot);
                dot = fmaf(z[4 * q + 3], e4.w, dot);
            }
            float dist = sen[k] - 2.f * dot;
            if (dist < best) { best = dist; bi = c0 + k; }
        }
    }
    g_idx[p] = bi;
}

__global__ __launch_bounds__(256)
void vq_loss(const float* __restrict__ ze, const float* __restrict__ E,
             float* __restrict__ zq)
{
    __shared__ int h[512];
    __shared__ float red[8];
    const int tid = threadIdx.x;
    for (int i = tid; i < 512; i += 256) h[i] = 0;
    __syncthreads();
    const int p = blockIdx.x * 256 + tid;
    const int b = p >> 10, s = p & 1023;
    const int id = g_idx[p];
    atomicAdd(&h[id], 1);
    const float* ep = E + id * 64;
    const float* zp = ze + (long)b * 65536 + s;
    float* qp = zq + (long)b * 65536 + s;
    float sse = 0.f;
#pragma unroll
    for (int d = 0; d < 64; d++) {
        float e = ep[d];
        float diff = e - zp[d * 1024];
        sse = fmaf(diff, diff, sse);
        qp[d * 1024] = e;
    }
#pragma unroll
    for (int off = 16; off; off >>= 1) sse += __shfl_down_sync(0xffffffffu, sse, off);
    if ((tid & 31) == 0) red[tid >> 5] = sse;
    __syncthreads();
    for (int i = tid; i < 512; i += 256)
        if (h[i]) atomicAdd(&g_cnt[i], h[i]);
    if (tid == 0) {
        float t = 0.f;
#pragma unroll
        for (int w = 0; w < 8; w++) t += red[w];
        atomicAdd(&g_sse, t);
    }
}

__global__ void clear_k()
{
    int t = threadIdx.x;
    if (t < 512) g_cnt[t] = 0;
    if (t == 0) g_sse = 0.f;
}

__global__ void finalize(float* __restrict__ out)
{
    __shared__ float red[512];
    int t = threadIdx.x;
    float cnt = (float)g_cnt[t];
    float pr = cnt * (1.f / 65536.f);
    red[t] = (cnt > 0.f) ? (-pr * log2f(pr + 1e-10f)) : 0.f;
    __syncthreads();
    for (int o = 256; o; o >>= 1) {
        if (t < o) red[t] += red[t + o];
        __syncthreads();
    }
    if (t == 0) {
        float ent = red[0];
        float mse = g_sse / (65536.f * 64.f);
        out[0] = 1.25f * mse;                 // e_and_q = q + 0.25*e
        out[1 + 3145728] = mse;               // e_latent_loss
        out[2 + 3145728] = mse;               // q_latent_loss
        out[3 + 3145728] = exp2f(ent);        // est_words
    }
}

// ---------------- host ----------------
extern "C" void kernel_launch(void* const* d_in, const int* in_sizes, int n_in,
                              void* d_out, int out_size)
{
    (void)in_sizes; (void)n_in; (void)out_size;
    const float* x        = (const float*)d_in[0];
    const float* enc_w1   = (const float*)d_in[1];
    const float* enc_b1   = (const float*)d_in[2];
    const float* enc_w2   = (const float*)d_in[3];
    const float* enc_b2   = (const float*)d_in[4];
    const float* enc_w3   = (const float*)d_in[5];
    const float* enc_b3   = (const float*)d_in[6];
    const float* enc_w4   = (const float*)d_in[7];
    const float* enc_b4   = (const float*)d_in[8];
    const float* eres_w1  = (const float*)d_in[9];
    const float* eres_w2  = (const float*)d_in[10];
    const float* eadj_w   = (const float*)d_in[11];
    const float* eadj_b   = (const float*)d_in[12];
    const float* E        = (const float*)d_in[13];
    const float* dadj_w   = (const float*)d_in[14];
    const float* dadj_b   = (const float*)d_in[15];
    const float* dres_w1  = (const float*)d_in[16];
    const float* dres_w2  = (const float*)d_in[17];
    const float* tc1_w    = (const float*)d_in[18];
    const float* tc1_b    = (const float*)d_in[19];
    const float* tc2_w    = (const float*)d_in[20];
    const float* tc2_b    = (const float*)d_in[21];

    float *h1, *a, *bb, *m, *ze, *zq, *wt;
    cudaGetSymbolAddress((void**)&h1, g_h1);
    cudaGetSymbolAddress((void**)&a,  g_a);
    cudaGetSymbolAddress((void**)&bb, g_b);
    cudaGetSymbolAddress((void**)&m,  g_m);
    cudaGetSymbolAddress((void**)&ze, g_ze);
    cudaGetSymbolAddress((void**)&zq, g_zq);
    cudaGetSymbolAddress((void**)&wt, g_wt);

    // weight transforms (tiny)
    auto T = [&](const float* w, float* dst, int CIN, int COUT, int K2, int tr) {
        int total = CIN * COUT * K2;
        wtrans<<<(total + 255) / 256, 256>>>(w, dst, CIN, COUT, K2, tr);
    };
    T(enc_w1,           wt + OFF_ENC1,    3,   64,  16, 0);
    T(enc_w2,           wt + OFF_ENC2,    64,  128, 16, 0);
    T(enc_w3,           wt + OFF_ENC3,    128, 128, 9,  0);
    T(enc_w4,           wt + OFF_ENC4,    128, 128, 9,  0);
    T(eres_w1,          wt + OFF_ERES1_0, 128, 64,  9,  0);
    T(eres_w1 + 73728,  wt + OFF_ERES1_1, 128, 64,  9,  0);
    T(eres_w2,          wt + OFF_ERES2_0, 64,  128, 1,  0);
    T(eres_w2 + 8192,   wt + OFF_ERES2_1, 64,  128, 1,  0);
    T(eadj_w,           wt + OFF_EADJ,    128, 64,  1,  0);
    T(dadj_w,           wt + OFF_DADJ,    64,  128, 9,  0);
    T(dres_w1,          wt + OFF_DRES1_0, 128, 64,  9,  0);
    T(dres_w1 + 73728,  wt + OFF_DRES1_1, 128, 64,  9,  0);
    T(dres_w2,          wt + OFF_DRES2_0, 64,  128, 1,  0);
    T(dres_w2 + 8192,   wt + OFF_DRES2_1, 64,  128, 1,  0);
    T(tc1_w,            wt + OFF_TC1,     128, 64,  16, 1);
    T(tc2_w,            wt + OFF_TC2,     64,  3,   16, 1);

    clear_k<<<1, 512>>>();
    vq_en<<<4, 128>>>(E);

    // ---- encoder ----
    conv_tiled<3, 64, 4, 2, 1, 3, false, true, true, false>
        <<<dim3(32, 1, 64), 256>>>(x, wt + OFF_ENC1, enc_b1, nullptr, h1, 128, 128, 64, 64, 4);
    conv_tiled<64, 128, 4, 2, 1, 8, false, true, true, false>
        <<<dim3(8, 2, 64), 256>>>(h1, wt + OFF_ENC2, enc_b2, nullptr, a, 64, 64, 32, 32, 2);
    conv_tiled<128, 128, 3, 1, 1, 8, false, true, true, false>
        <<<dim3(8, 2, 64), 256>>>(a, wt + OFF_ENC3, enc_b3, nullptr, bb, 32, 32, 32, 32, 2);
    conv_tiled<128, 128, 3, 1, 1, 8, false, true, false, false>
        <<<dim3(8, 2, 64), 256>>>(bb, wt + OFF_ENC4, enc_b4, nullptr, a, 32, 32, 32, 32, 2);
    // enc res block 0
    conv_tiled<128, 64, 3, 1, 1, 8, true, false, false, false>
        <<<dim3(8, 1, 64), 256>>>(a, wt + OFF_ERES1_0, nullptr, nullptr, m, 32, 32, 32, 32, 2);
    conv_tiled<64, 128, 1, 1, 0, 8, true, false, false, true>
        <<<dim3(8, 2, 64), 256>>>(m, wt + OFF_ERES2_0, nullptr, a, a, 32, 32, 32, 32, 2);
    // enc res block 1
    conv_tiled<128, 64, 3, 1, 1, 8, true, false, false, false>
        <<<dim3(8, 1, 64), 256>>>(a, wt + OFF_ERES1_1, nullptr, nullptr, m, 32, 32, 32, 32, 2);
    conv_tiled<64, 128, 1, 1, 0, 8, true, false, false, true>
        <<<dim3(8, 2, 64), 256>>>(m, wt + OFF_ERES2_1, nullptr, a, a, 32, 32, 32, 32, 2);
    // enc_adj consumes relu(res_stack output)
    conv_tiled<128, 64, 1, 1, 0, 8, true, true, false, false>
        <<<dim3(8, 1, 64), 256>>>(a, wt + OFF_EADJ, eadj_b, nullptr, ze, 32, 32, 32, 32, 2);

    // ---- vector quantizer ----
    vq_argmin<<<256, 256>>>(ze, E);
    vq_loss<<<256, 256>>>(ze, E, zq);

    // ---- decoder ----
    conv_tiled<64, 128, 3, 1, 1, 8, false, true, false, false>
        <<<dim3(8, 2, 64), 256>>>(zq, wt + OFF_DADJ, dadj_b, nullptr, a, 32, 32, 32, 32, 2);
    // dec res block 0
    conv_tiled<128, 64, 3, 1, 1, 8, true, false, false, false>
        <<<dim3(8, 1, 64), 256>>>(a, wt + OFF_DRES1_0, nullptr, nullptr, m, 32, 32, 32, 32, 2);
    conv_tiled<64, 128, 1, 1, 0, 8, true, false, false, true>
        <<<dim3(8, 2, 64), 256>>>(m, wt + OFF_DRES2_0, nullptr, a, a, 32, 32, 32, 32, 2);
    // dec res block 1
    conv_tiled<128, 64, 3, 1, 1, 8, true, false, false, false>
        <<<dim3(8, 1, 64), 256>>>(a, wt + OFF_DRES1_1, nullptr, nullptr, m, 32, 32, 32, 32, 2);
    conv_tiled<64, 128, 1, 1, 0, 8, true, false, false, true>
        <<<dim3(8, 2, 64), 256>>>(m, wt + OFF_DRES2_1, nullptr, a, a, 32, 32, 32, 32, 2);
    // tc1 consumes relu(res_stack output)
    convt_tiled<128, 64, true, true>
        <<<dim3(32, 1, 64), 256>>>(a, wt + OFF_TC1, tc1_b, h1, 32, 32, 64, 64, 4);
    // tc2 -> x_recon straight into d_out (offset 1)
    convt_c3<<<dim3(64, 1, 64), 256>>>(h1, wt + OFF_TC2, tc2_b, (float*)d_out + 1);

    finalize<<<1, 512>>>((float*)d_out);
}

// round 5
// speedup vs baseline: 2.1933x; 2.1865x over previous
#include <cuda_runtime.h>
#include <math.h>
#include <float.h>

// ---------------- scratch (device globals; no allocation allowed) ----------------
__device__ float g_h1[64 * 64 * 64 * 64];   // (64,64,64,64) NHWC
__device__ float g_a [64 * 32 * 32 * 128];  // (64,32,32,128) NHWC
__device__ float g_b [64 * 32 * 32 * 128];
__device__ float g_m [64 * 32 * 32 * 64];
__device__ float g_ze[64 * 32 * 32 * 64];   // flat (65536,64)
__device__ float g_zq[64 * 32 * 32 * 64];
__device__ float g_wt[972800];
__device__ float g_En[512];
__device__ int   g_cnt[512];
__device__ float g_sse;

#define OFF_ENC1     0        // 3*16*64     = 3072   (FFMA layout)
#define OFF_ENC2     3072     // 16*64*128   = 131072 (mma layout: tap,ci,co)
#define OFF_ENC3     134144   // 9*128*128   = 147456
#define OFF_ENC4     281600
#define OFF_ERES1_0  429056   // 9*128*64    = 73728
#define OFF_ERES1_1  502784
#define OFF_ERES2_0  576512   // 1*64*128    = 8192
#define OFF_ERES2_1  584704
#define OFF_EADJ     592896   // 1*128*64    = 8192
#define OFF_DADJ     601088   // 9*64*128    = 73728
#define OFF_DRES1_0  674816
#define OFF_DRES1_1  748544
#define OFF_DRES2_0  822272
#define OFF_DRES2_1  830464
#define OFF_TC1      838656   // 4 parities * 4*128*64 = 131072
#define OFF_TC2      969728   // 64*16*3 = 3072 (FFMA layout)

// ---------------- helpers ----------------
__device__ __forceinline__ unsigned f2tf(float f) {
    unsigned u; asm("cvt.rna.tf32.f32 %0, %1;" : "=r"(u) : "f"(f)); return u;
}
__device__ __forceinline__ float tf32r(float f) {
    return __uint_as_float(f2tf(f));
}
__device__ __forceinline__ void mma8(float* c, const unsigned* a, const unsigned* b) {
    asm volatile(
        "mma.sync.aligned.m16n8k8.row.col.f32.tf32.tf32.f32 "
        "{%0,%1,%2,%3},{%4,%5,%6,%7},{%8,%9},{%0,%1,%2,%3};"
        : "+f"(c[0]), "+f"(c[1]), "+f"(c[2]), "+f"(c[3])
        : "r"(a[0]), "r"(a[1]), "r"(a[2]), "r"(a[3]), "r"(b[0]), "r"(b[1]));
}

// ---------------- weight transforms ----------------
// FFMA layout (enc1/tc2): dst[(ci*K2+kk)*COUT+co]
__global__ void wtrans(const float* __restrict__ w, float* __restrict__ wt,
                       int CIN, int COUT, int K2, int transposed)
{
    int i = blockIdx.x * 256 + threadIdx.x;
    int total = CIN * COUT * K2;
    if (i >= total) return;
    int co = i % COUT;
    int t  = i / COUT;
    int kk = t % K2;
    int ci = t / K2;
    float v = transposed ? w[(ci * COUT + co) * K2 + kk]
                         : w[(co * CIN + ci) * K2 + kk];
    wt[i] = v;
}

// mma layout (conv OIHW): dst[(tap*CIN+ci)*COUT+co]
__global__ void wtrans_mma(const float* __restrict__ w, float* __restrict__ wt,
                           int CIN, int COUT, int K2)
{
    int i = blockIdx.x * 256 + threadIdx.x;
    int total = CIN * COUT * K2;
    if (i >= total) return;
    int co = i % COUT;
    int t  = i / COUT;
    int ci = t % CIN;
    int tap = t / CIN;
    wt[i] = w[(co * CIN + ci) * K2 + tap];
}

// tc1 parity repack: convT w (128,64,4,4) -> 4 parity sets of [(ky'2+kx')*128+ci][64]
__global__ void wtrans_tc1(const float* __restrict__ w, float* __restrict__ wt)
{
    int i = blockIdx.x * 256 + threadIdx.x;   // total 4*4*128*64 = 131072
    if (i >= 131072) return;
    int co = i & 63;
    int r = i >> 6;
    int ci = r & 127; r >>= 7;
    int t = r & 3;    r >>= 2;       // tap: ky'*2+kx'
    int p = r;                        // parity: py*2+px
    int py = p >> 1, px = p & 1;
    int kyp = t >> 1, kxp = t & 1;
    int ky = py ? (2 - 2 * kyp) : (3 - 2 * kyp);
    int kx = px ? (2 - 2 * kxp) : (3 - 2 * kxp);
    wt[i] = w[(ci * 64 + co) * 16 + ky * 4 + kx];
}

// ---------------- tensor-core implicit-GEMM conv ----------------
// Block: 128 output px (4 rows x 32 cols of a 32x32 class grid) x COUT.
// 8 warps: 4 (px rows) x 2 (co halves). Warp: 32px x COUT/2.
// Inputs NHWC fp32; staged to smem pre-rounded to tf32.
template<int CIN, int COUT, int KS, int S, int TAPCH,
         bool RELU_IN, bool HAS_BIAS, bool RELU_OUT, bool ADD_RES>
__global__ __launch_bounds__(256, 2)
void conv_mma(const float* __restrict__ in, const float* __restrict__ wt,
              const float* __restrict__ bias, const float* __restrict__ res,
              float* __restrict__ out, int H, int W, int PY, int PX,
              int OHF, int OWF, int OY0, int OYS, int OX0, int OXS)
{
    constexpr int CICH = 8;
    constexpr int ITH = 3 * S + KS;
    constexpr int ITW = 31 * S + KS;
    constexpr int RAW = ITH * ITW;
    constexpr int PLANE = ((RAW + 31) & ~31) + 8;   // %32 == 8 -> conflict-free A frags
    constexpr int BNP = COUT + 8;                   // %32 == 8 -> conflict-free B frags
    constexpr int NSUB = COUT / 16;                 // B subtiles per warp
    constexpr int NTAPS = KS * KS;
    constexpr int NSTG = NTAPS / TAPCH;

    __shared__ __align__(16) float sA[CICH * PLANE];
    __shared__ __align__(16) float sB[TAPCH * CICH * BNP];

    const int ty = blockIdx.x;          // 0..7, 4 output rows each
    const int n  = blockIdx.z;
    const int tid = threadIdx.x;
    const int lane = tid & 31, wid = tid >> 5;
    const int wm = wid & 3, wn = wid >> 2;

    float c[2][NSUB][4];
#pragma unroll
    for (int mt = 0; mt < 2; mt++)
#pragma unroll
        for (int ns = 0; ns < NSUB; ns++)
#pragma unroll
            for (int q = 0; q < 4; q++) c[mt][ns][q] = 0.f;

    const int oyb = ty * 4;
    const int iy0 = oyb * S - PY;
    const int ix0 = -PX;
    const float* inb = in + (long)n * H * W * CIN;

    for (int cc = 0; cc < CIN; cc += CICH) {
        for (int st = 0; st < NSTG; st++) {
            if (st == 0) {
                for (int i = tid; i < CICH * RAW; i += 256) {
                    int ci = i & 7;
                    int pix = i >> 3;
                    int iy = pix / ITW, ix = pix - iy * ITW;
                    int gy = iy0 + iy, gx = ix0 + ix;
                    float v = 0.f;
                    if ((unsigned)gy < (unsigned)H && (unsigned)gx < (unsigned)W)
                        v = inb[((long)gy * W + gx) * CIN + cc + ci];
                    if (RELU_IN) v = fmaxf(v, 0.f);
                    sA[ci * PLANE + pix] = tf32r(v);
                }
            }
            {
                const float* wsrc = wt + ((long)(st * TAPCH) * CIN + cc) * COUT;
                for (int i = tid * 4; i < TAPCH * CICH * COUT; i += 1024) {
                    int t = i / (CICH * COUT);
                    int rem = i - t * (CICH * COUT);
                    int ci = rem / COUT;
                    int co = rem - ci * COUT;
                    float4 v = *(const float4*)(wsrc + ((long)t * CIN + ci) * COUT + co);
                    v.x = tf32r(v.x); v.y = tf32r(v.y); v.z = tf32r(v.z); v.w = tf32r(v.w);
                    *(float4*)(sB + (t * CICH + ci) * BNP + co) = v;
                }
            }
            __syncthreads();
#pragma unroll
            for (int tl = 0; tl < TAPCH; tl++) {
                const int tap = st * TAPCH + tl;
                const int ky = tap / KS, kx = tap - ky * KS;
                const unsigned* pa = (const unsigned*)sA + (lane & 3) * PLANE
                                   + (wm * S + ky) * ITW + (lane >> 2) * S + kx;
                unsigned a[2][4];
#pragma unroll
                for (int mt = 0; mt < 2; mt++) {
                    const unsigned* p = pa + mt * 16 * S;
                    a[mt][0] = p[0];
                    a[mt][1] = p[8 * S];
                    a[mt][2] = p[4 * PLANE];
                    a[mt][3] = p[4 * PLANE + 8 * S];
                }
                const unsigned* pb = (const unsigned*)sB + (tl * CICH + (lane & 3)) * BNP
                                   + wn * (COUT / 2) + (lane >> 2);
                unsigned b[NSUB][2];
#pragma unroll
                for (int ns = 0; ns < NSUB; ns++) {
                    b[ns][0] = pb[ns * 8];
                    b[ns][1] = pb[ns * 8 + 4 * BNP];
                }
#pragma unroll
                for (int mt = 0; mt < 2; mt++)
#pragma unroll
                    for (int ns = 0; ns < NSUB; ns++)
                        mma8(c[mt][ns], a[mt], b[ns]);
            }
            __syncthreads();
        }
    }

    // epilogue
    const int oy = oyb + wm;
    const int gy = OY0 + oy * OYS;
    const long nb = ((long)n * OHF + gy) * OWF;
#pragma unroll
    for (int mt = 0; mt < 2; mt++) {
#pragma unroll
        for (int half = 0; half < 2; half++) {
            int ox = mt * 16 + (lane >> 2) + half * 8;
            int gx = OX0 + ox * OXS;
            long pxbase = (nb + gx) * COUT;
#pragma unroll
            for (int ns = 0; ns < NSUB; ns++) {
                int co = wn * (COUT / 2) + ns * 8 + 2 * (lane & 3);
                long idx = pxbase + co;
                float v0 = c[mt][ns][half * 2 + 0];
                float v1 = c[mt][ns][half * 2 + 1];
                if (HAS_BIAS) {
                    float2 bb = *(const float2*)(bias + co);
                    v0 += bb.x; v1 += bb.y;
                }
                if (ADD_RES) {
                    float2 rr = *(const float2*)(res + idx);
                    v0 += rr.x; v1 += rr.y;
                }
                if (RELU_OUT) { v0 = fmaxf(v0, 0.f); v1 = fmaxf(v1, 0.f); }
                *(float2*)(out + idx) = make_float2(v0, v1);
            }
        }
    }
}

// ---------------- enc1: NCHW in (3ch) -> NHWC out, FFMA ----------------
__global__ __launch_bounds__(256)
void enc1_k(const float* __restrict__ in, const float* __restrict__ wt,
            const float* __restrict__ bias, float* __restrict__ out)
{
    constexpr int ITH = 18, ITW = 34;   // KS=4,S=2,P=1, 8x16 out tile
    __shared__ float sm[3 * ITH * ITW];
    const int tile = blockIdx.x;        // TX=4, TY=8 -> 32
    const int tx = tile & 3, ty = tile >> 2;
    const int n = blockIdx.z;
    const int tid = threadIdx.x;
    const int ocl = (tid & 15) << 2;
    const int pg = tid >> 4;
    const int r = pg >> 1, ch = pg & 1;

    float acc[4][8];
#pragma unroll
    for (int o = 0; o < 4; o++)
#pragma unroll
        for (int p = 0; p < 8; p++) acc[o][p] = 0.f;

    const int iy0 = ty * 16 - 1, ix0 = tx * 32 - 1;
    const float* inb = in + (long)n * 3 * 128 * 128;

    for (int i = tid; i < 3 * ITH * ITW; i += 256) {
        int ci = i / (ITH * ITW);
        int rem = i - ci * (ITH * ITW);
        int iy = rem / ITW, ix = rem - iy * ITW;
        int gy = iy0 + iy, gx = ix0 + ix;
        float v = 0.f;
        if ((unsigned)gy < 128u && (unsigned)gx < 128u)
            v = inb[ci * 16384 + gy * 128 + gx];
        sm[i] = v;
    }
    __syncthreads();
#pragma unroll
    for (int ci = 0; ci < 3; ci++) {
        const float* sp = sm + ci * ITH * ITW + (r * 2) * ITW + (ch * 16);
        const float* wp = wt + (ci * 16) * 64 + ocl;
#pragma unroll
        for (int ky = 0; ky < 4; ky++) {
#pragma unroll
            for (int kx = 0; kx < 4; kx++) {
                float4 w4 = *(const float4*)(wp + (ky * 4 + kx) * 64);
                const float* sr = sp + ky * ITW + kx;
#pragma unroll
                for (int px = 0; px < 8; px++) {
                    float xv = sr[px * 2];
                    acc[0][px] = fmaf(w4.x, xv, acc[0][px]);
                    acc[1][px] = fmaf(w4.y, xv, acc[1][px]);
                    acc[2][px] = fmaf(w4.z, xv, acc[2][px]);
                    acc[3][px] = fmaf(w4.w, xv, acc[3][px]);
                }
            }
        }
    }
    float4 b4 = *(const float4*)(bias + ocl);
    const int oy = ty * 8 + r;
    const int oxb = tx * 16 + ch * 8;
#pragma unroll
    for (int px = 0; px < 8; px++) {
        float4 v;
        v.x = fmaxf(acc[0][px] + b4.x, 0.f);
        v.y = fmaxf(acc[1][px] + b4.y, 0.f);
        v.z = fmaxf(acc[2][px] + b4.z, 0.f);
        v.w = fmaxf(acc[3][px] + b4.w, 0.f);
        *(float4*)(out + (((long)n * 64 + oy) * 64 + oxb + px) * 64 + ocl) = v;
    }
}

// ---------------- tc2: NHWC in -> NCHW out (3ch), FFMA ----------------
__global__ __launch_bounds__(256)
void convt_c3(const float* __restrict__ in, const float* __restrict__ wt,
              const float* __restrict__ bias, float* __restrict__ out)
{
    __shared__ float swt[64 * 16 * 3];
    __shared__ float sin_[6 * 18 * 8];
    const int tile = blockIdx.x;              // TX=4, TY=16
    const int tx = tile & 3, ty = tile >> 2;
    const int n = blockIdx.z;
    const int tid = threadIdx.x;
    for (int i = tid; i < 3072; i += 256) swt[i] = wt[i];

    const int r = tid >> 5, c = tid & 31;
    const int oy = ty * 8 + r, ox = tx * 32 + c;
    const int iyb = ty * 4 - 1, ixb = tx * 16 - 1;
    const int pey = oy & 1, pex = ox & 1;
    float a0 = 0.f, a1 = 0.f, a2 = 0.f;
    const float* inb = in + (long)n * 64 * 64 * 64;

    for (int cc = 0; cc < 64; cc += 8) {
        __syncthreads();
        for (int i = tid; i < 6 * 18 * 8; i += 256) {
            int ci = i & 7;
            int pix = i >> 3;
            int iy = pix / 18, ix = pix - iy * 18;
            int gy = iyb + iy, gx = ixb + ix;
            float v = 0.f;
            if ((unsigned)gy < 64u && (unsigned)gx < 64u)
                v = inb[((long)gy * 64 + gx) * 64 + cc + ci];
            sin_[pix * 8 + ci] = v;
        }
        __syncthreads();
#pragma unroll 1
        for (int ci = 0; ci < 8; ci++) {
#pragma unroll
            for (int jy = 0; jy < 2; jy++) {
                int ly = ((oy + 1) >> 1) - jy - iyb;
                int ky = (1 - pey) + 2 * jy;
#pragma unroll
                for (int jx = 0; jx < 2; jx++) {
                    int lx = ((ox + 1) >> 1) - jx - ixb;
                    int kx = (1 - pex) + 2 * jx;
                    float xv = sin_[(ly * 18 + lx) * 8 + ci];
                    const float* w = swt + ((cc + ci) * 16 + ky * 4 + kx) * 3;
                    a0 = fmaf(xv, w[0], a0);
                    a1 = fmaf(xv, w[1], a1);
                    a2 = fmaf(xv, w[2], a2);
                }
            }
        }
    }
    long base = (long)n * 3 * 128 * 128 + oy * 128 + ox;
    out[base]         = a0 + bias[0];
    out[base + 16384] = a1 + bias[1];
    out[base + 32768] = a2 + bias[2];
}

// ---------------- VQ ----------------
__global__ void vq_en(const float* __restrict__ E)
{
    int k = blockIdx.x * 128 + threadIdx.x;
    if (k < 512) {
        float s = 0.f;
#pragma unroll
        for (int d = 0; d < 64; d++) { float e = E[k * 64 + d]; s = fmaf(e, e, s); }
        g_En[k] = s;
    }
}

__global__ __launch_bounds__(256)
void vq_fused(const float* __restrict__ ze, const float* __restrict__ E,
              float* __restrict__ zq)
{
    __shared__ float se[64 * 64];
    __shared__ float sen[64];
    __shared__ int h[512];
    __shared__ float red[8];
    const int tid = threadIdx.x;
    for (int i = tid; i < 512; i += 256) h[i] = 0;
    const int p = blockIdx.x * 256 + tid;
    float z[64];
    const float4* zp4 = (const float4*)(ze + (long)p * 64);
#pragma unroll
    for (int q = 0; q < 16; q++) {
        float4 v = zp4[q];
        z[4 * q] = v.x; z[4 * q + 1] = v.y; z[4 * q + 2] = v.z; z[4 * q + 3] = v.w;
    }
    float best = FLT_MAX;
    int bi = 0;
    for (int c0 = 0; c0 < 512; c0 += 64) {
        __syncthreads();
        for (int i = tid; i < 4096; i += 256) se[i] = E[c0 * 64 + i];
        if (tid < 64) sen[tid] = g_En[c0 + tid];
        __syncthreads();
        for (int k = 0; k < 64; k++) {
            const float4* ep = (const float4*)(se + k * 64);
            float dot = 0.f;
#pragma unroll
            for (int q = 0; q < 16; q++) {
                float4 e4 = ep[q];
                dot = fmaf(z[4 * q + 0], e4.x, dot);
                dot = fmaf(z[4 * q + 1], e4.y, dot);
                dot = fmaf(z[4 * q + 2], e4.z, dot);
                dot = fmaf(z[4 * q + 3], e4.w, dot);
            }
            float dist = sen[k] - 2.f * dot;
            if (dist < best) { best = dist; bi = c0 + k; }
        }
    }
    // gather + loss + hist
    atomicAdd(&h[bi], 1);
    const float4* ep4 = (const float4*)(E + (long)bi * 64);
    float4* qp4 = (float4*)(zq + (long)p * 64);
    float sse = 0.f;
#pragma unroll
    for (int q = 0; q < 16; q++) {
        float4 e4 = ep4[q];
        float d0 = e4.x - z[4 * q + 0];
        float d1 = e4.y - z[4 * q + 1];
        float d2 = e4.z - z[4 * q + 2];
        float d3 = e4.w - z[4 * q + 3];
        sse = fmaf(d0, d0, sse); sse = fmaf(d1, d1, sse);
        sse = fmaf(d2, d2, sse); sse = fmaf(d3, d3, sse);
        qp4[q] = e4;
    }
#pragma unroll
    for (int off = 16; off; off >>= 1) sse += __shfl_down_sync(0xffffffffu, sse, off);
    if ((tid & 31) == 0) red[tid >> 5] = sse;
    __syncthreads();
    for (int i = tid; i < 512; i += 256)
        if (h[i]) atomicAdd(&g_cnt[i], h[i]);
    if (tid == 0) {
        float t = 0.f;
#pragma unroll
        for (int w = 0; w < 8; w++) t += red[w];
        atomicAdd(&g_sse, t);
    }
}

__global__ void clear_k()
{
    int t = threadIdx.x;
    if (t < 512) g_cnt[t] = 0;
    if (t == 0) g_sse = 0.f;
}

__global__ void finalize(float* __restrict__ out)
{
    __shared__ float red[512];
    int t = threadIdx.x;
    float cnt = (float)g_cnt[t];
    float pr = cnt * (1.f / 65536.f);
    red[t] = (cnt > 0.f) ? (-pr * log2f(pr + 1e-10f)) : 0.f;
    __syncthreads();
    for (int o = 256; o; o >>= 1) {
        if (t < o) red[t] += red[t + o];
        __syncthreads();
    }
    if (t == 0) {
        float ent = red[0];
        float mse = g_sse / (65536.f * 64.f);
        out[0] = 1.25f * mse;
        out[1 + 3145728] = mse;
        out[2 + 3145728] = mse;
        out[3 + 3145728] = exp2f(ent);
    }
}

// ---------------- host ----------------
extern "C" void kernel_launch(void* const* d_in, const int* in_sizes, int n_in,
                              void* d_out, int out_size)
{
    (void)in_sizes; (void)n_in; (void)out_size;
    const float* x        = (const float*)d_in[0];
    const float* enc_w1   = (const float*)d_in[1];
    const float* enc_b1   = (const float*)d_in[2];
    const float* enc_w2   = (const float*)d_in[3];
    const float* enc_b2   = (const float*)d_in[4];
    const float* enc_w3   = (const float*)d_in[5];
    const float* enc_b3   = (const float*)d_in[6];
    const float* enc_w4   = (const float*)d_in[7];
    const float* enc_b4   = (const float*)d_in[8];
    const float* eres_w1  = (const float*)d_in[9];
    const float* eres_w2  = (const float*)d_in[10];
    const float* eadj_w   = (const float*)d_in[11];
    const float* eadj_b   = (const float*)d_in[12];
    const float* E        = (const float*)d_in[13];
    const float* dadj_w   = (const float*)d_in[14];
    const float* dadj_b   = (const float*)d_in[15];
    const float* dres_w1  = (const float*)d_in[16];
    const float* dres_w2  = (const float*)d_in[17];
    const float* tc1_w    = (const float*)d_in[18];
    const float* tc1_b    = (const float*)d_in[19];
    const float* tc2_w    = (const float*)d_in[20];
    const float* tc2_b    = (const float*)d_in[21];

    float *h1, *a, *bb, *m, *ze, *zq, *wt;
    cudaGetSymbolAddress((void**)&h1, g_h1);
    cudaGetSymbolAddress((void**)&a,  g_a);
    cudaGetSymbolAddress((void**)&bb, g_b);
    cudaGetSymbolAddress((void**)&m,  g_m);
    cudaGetSymbolAddress((void**)&ze, g_ze);
    cudaGetSymbolAddress((void**)&zq, g_zq);
    cudaGetSymbolAddress((void**)&wt, g_wt);

    auto TM = [&](const float* w, float* dst, int CIN, int COUT, int K2) {
        int total = CIN * COUT * K2;
        wtrans_mma<<<(total + 255) / 256, 256>>>(w, dst, CIN, COUT, K2);
    };
    wtrans<<<12, 256>>>(enc_w1, wt + OFF_ENC1, 3, 64, 16, 0);
    TM(enc_w2,          wt + OFF_ENC2,    64,  128, 16);
    TM(enc_w3,          wt + OFF_ENC3,    128, 128, 9);
    TM(enc_w4,          wt + OFF_ENC4,    128, 128, 9);
    TM(eres_w1,         wt + OFF_ERES1_0, 128, 64,  9);
    TM(eres_w1 + 73728, wt + OFF_ERES1_1, 128, 64,  9);
    TM(eres_w2,         wt + OFF_ERES2_0, 64,  128, 1);
    TM(eres_w2 + 8192,  wt + OFF_ERES2_1, 64,  128, 1);
    TM(eadj_w,          wt + OFF_EADJ,    128, 64,  1);
    TM(dadj_w,          wt + OFF_DADJ,    64,  128, 9);
    TM(dres_w1,         wt + OFF_DRES1_0, 128, 64,  9);
    TM(dres_w1 + 73728, wt + OFF_DRES1_1, 128, 64,  9);
    TM(dres_w2,         wt + OFF_DRES2_0, 64,  128, 1);
    TM(dres_w2 + 8192,  wt + OFF_DRES2_1, 64,  128, 1);
    wtrans_tc1<<<512, 256>>>(tc1_w, wt + OFF_TC1);
    wtrans<<<12, 256>>>(tc2_w, wt + OFF_TC2, 64, 3, 16, 1);

    clear_k<<<1, 512>>>();
    vq_en<<<4, 128>>>(E);

    const dim3 G(8, 1, 64);
    // ---- encoder ----
    enc1_k<<<dim3(32, 1, 64), 256>>>(x, wt + OFF_ENC1, enc_b1, h1);
    conv_mma<64, 128, 4, 2, 4, false, true, true, false>
        <<<G, 256>>>(h1, wt + OFF_ENC2, enc_b2, nullptr, a, 64, 64, 1, 1, 32, 32, 0, 1, 0, 1);
    conv_mma<128, 128, 3, 1, 9, false, true, true, false>
        <<<G, 256>>>(a, wt + OFF_ENC3, enc_b3, nullptr, bb, 32, 32, 1, 1, 32, 32, 0, 1, 0, 1);
    conv_mma<128, 128, 3, 1, 9, false, true, false, false>
        <<<G, 256>>>(bb, wt + OFF_ENC4, enc_b4, nullptr, a, 32, 32, 1, 1, 32, 32, 0, 1, 0, 1);
    conv_mma<128, 64, 3, 1, 9, true, false, false, false>
        <<<G, 256>>>(a, wt + OFF_ERES1_0, nullptr, nullptr, m, 32, 32, 1, 1, 32, 32, 0, 1, 0, 1);
    conv_mma<64, 128, 1, 1, 1, true, false, false, true>
        <<<G, 256>>>(m, wt + OFF_ERES2_0, nullptr, a, a, 32, 32, 0, 0, 32, 32, 0, 1, 0, 1);
    conv_mma<128, 64, 3, 1, 9, true, false, false, false>
        <<<G, 256>>>(a, wt + OFF_ERES1_1, nullptr, nullptr, m, 32, 32, 1, 1, 32, 32, 0, 1, 0, 1);
    conv_mma<64, 128, 1, 1, 1, true, false, false, true>
        <<<G, 256>>>(m, wt + OFF_ERES2_1, nullptr, a, a, 32, 32, 0, 0, 32, 32, 0, 1, 0, 1);
    conv_mma<128, 64, 1, 1, 1, true, true, false, false>
        <<<G, 256>>>(a, wt + OFF_EADJ, eadj_b, nullptr, ze, 32, 32, 0, 0, 32, 32, 0, 1, 0, 1);

    // ---- VQ ----
    vq_fused<<<256, 256>>>(ze, E, zq);

    // ---- decoder ----
    conv_mma<64, 128, 3, 1, 9, false, true, false, false>
        <<<G, 256>>>(zq, wt + OFF_DADJ, dadj_b, nullptr, a, 32, 32, 1, 1, 32, 32, 0, 1, 0, 1);
    conv_mma<128, 64, 3, 1, 9, true, false, false, false>
        <<<G, 256>>>(a, wt + OFF_DRES1_0, nullptr, nullptr, m, 32, 32, 1, 1, 32, 32, 0, 1, 0, 1);
    conv_mma<64, 128, 1, 1, 1, true, false, false, true>
        <<<G, 256>>>(m, wt + OFF_DRES2_0, nullptr, a, a, 32, 32, 0, 0, 32, 32, 0, 1, 0, 1);
    conv_mma<128, 64, 3, 1, 9, true, false, false, false>
        <<<G, 256>>>(a, wt + OFF_DRES1_1, nullptr, nullptr, m, 32, 32, 1, 1, 32, 32, 0, 1, 0, 1);
    conv_mma<64, 128, 1, 1, 1, true, false, false, true>
        <<<G, 256>>>(m, wt + OFF_DRES2_1, nullptr, a, a, 32, 32, 0, 0, 32, 32, 0, 1, 0, 1);
    // tc1: 4 parity classes, each a 2x2 stride-1 conv over 32x32 -> interleaved 64x64
    for (int p = 0; p < 4; p++) {
        int py = p >> 1, px = p & 1;
        conv_mma<128, 64, 2, 1, 4, true, true, true, false>
            <<<G, 256>>>(a, wt + OFF_TC1 + p * 32768, tc1_b, nullptr, h1,
                         32, 32, py ? 0 : 1, px ? 0 : 1, 64, 64, py, 2, px, 2);
    }
    convt_c3<<<dim3(64, 1, 64), 256>>>(h1, wt + OFF_TC2, tc2_b, (float*)d_out + 1);

    finalize<<<1, 512>>>((float*)d_out);
}

// round 7
// speedup vs baseline: 2.3750x; 1.0828x over previous
#include <cuda_runtime.h>
#include <math.h>
#include <float.h>

// ---------------- scratch (device globals; no allocation allowed) ----------------
__device__ float g_h1[64 * 64 * 64 * 64];   // (64,64,64,64) NHWC
__device__ float g_a [64 * 32 * 32 * 128];  // (64,32,32,128) NHWC
__device__ float g_b [64 * 32 * 32 * 128];
__device__ float g_m [64 * 32 * 32 * 64];
__device__ float g_ze[64 * 32 * 32 * 64];   // flat (65536,64)
__device__ float g_zq[64 * 32 * 32 * 64];
__device__ float g_wt[972800];
__device__ float g_En[512];
__device__ int   g_cnt[512];
__device__ float g_sse;

#define OFF_ENC1     0        // 3*16*64     = 3072   (FFMA layout)
#define OFF_ENC2     3072     // 16*64*128   = 131072 (mma: [tap][ci8][co][8])
#define OFF_ENC3     134144   // 9*128*128   = 147456
#define OFF_ENC4     281600
#define OFF_ERES1_0  429056   // 9*128*64    = 73728
#define OFF_ERES1_1  502784
#define OFF_ERES2_0  576512   // 1*64*128    = 8192
#define OFF_ERES2_1  584704
#define OFF_EADJ     592896   // 1*128*64    = 8192
#define OFF_DADJ     601088   // 9*64*128    = 73728
#define OFF_DRES1_0  674816
#define OFF_DRES1_1  748544
#define OFF_DRES2_0  822272
#define OFF_DRES2_1  830464
#define OFF_TC1      838656   // 4 parities * 4*16*64*8 = 131072
#define OFF_TC2      969728   // 64*16*3 = 3072 (FFMA layout)

// ---------------- helpers ----------------
__device__ __forceinline__ float tf32r(float f) {
    unsigned u; asm("cvt.rna.tf32.f32 %0, %1;" : "=r"(u) : "f"(f));
    return __uint_as_float(u);
}
__device__ __forceinline__ float4 tf4(float4 v) {
    v.x = tf32r(v.x); v.y = tf32r(v.y); v.z = tf32r(v.z); v.w = tf32r(v.w);
    return v;
}
__device__ __forceinline__ void mma8(float* c, const unsigned* a, const unsigned* b) {
    asm volatile(
        "mma.sync.aligned.m16n8k8.row.col.f32.tf32.tf32.f32 "
        "{%0,%1,%2,%3},{%4,%5,%6,%7},{%8,%9},{%0,%1,%2,%3};"
        : "+f"(c[0]), "+f"(c[1]), "+f"(c[2]), "+f"(c[3])
        : "r"(a[0]), "r"(a[1]), "r"(a[2]), "r"(a[3]), "r"(b[0]), "r"(b[1]));
}
__device__ __forceinline__ void ldsm4(unsigned& r0, unsigned& r1, unsigned& r2, unsigned& r3,
                                      unsigned addr) {
    asm volatile("ldmatrix.sync.aligned.m8n8.x4.shared.b16 {%0,%1,%2,%3}, [%4];"
                 : "=r"(r0), "=r"(r1), "=r"(r2), "=r"(r3) : "r"(addr));
}

// ---------------- fused weight transforms ----------------
struct WArgs { const float* s[11]; };

// type 0 (mma):  dst[((tap*(CIN/8)+c8)*COUT+co)*8+cl] = w[(co*CIN + c8*8+cl)*K2 + tap]
// type 1 (ffma): dst[(ci*K2+kk)*COUT+co]              = w[(co*CIN+ci)*K2+kk]
// type 2 (ffmaT):dst[(ci*K2+kk)*COUT+co]              = w[(ci*COUT+co)*K2+kk]
__global__ void wtrans_all(WArgs A, float* __restrict__ wt)
{
    const short typ[15]  = {1,0,0,0,0,0,0,0,0,0,0,0,0,0,2};
    const short sidx[15] = {0,1,2,3,4,4,5,5,6,7,8,8,9,9,10};
    const int   soff[15] = {0,0,0,0,0,73728,0,8192,0,0,0,73728,0,8192,0};
    const short cin_[15] = {3,64,128,128,128,128,64,64,128,64,128,128,64,64,64};
    const short cout_[15]= {64,128,128,128,64,64,128,128,64,128,64,64,128,128,3};
    const short k2_[15]  = {16,16,9,9,9,9,1,1,1,9,9,9,1,1,16};
    const int   doff[15] = {OFF_ENC1,OFF_ENC2,OFF_ENC3,OFF_ENC4,OFF_ERES1_0,OFF_ERES1_1,
                            OFF_ERES2_0,OFF_ERES2_1,OFF_EADJ,OFF_DADJ,OFF_DRES1_0,OFF_DRES1_1,
                            OFF_DRES2_0,OFF_DRES2_1,OFF_TC2};
    const int gs = gridDim.x * blockDim.x;
    const int g0 = blockIdx.x * blockDim.x + threadIdx.x;
#pragma unroll 1
    for (int l = 0; l < 15; l++) {
        const float* w = A.s[sidx[l]] + soff[l];
        float* dst = wt + doff[l];
        const int CIN = cin_[l], COUT = cout_[l], K2 = k2_[l];
        const int n = CIN * COUT * K2;
        const int t = typ[l];
        for (int i = g0; i < n; i += gs) {
            float v;
            if (t == 0) {
                int cl = i & 7; int r = i >> 3;
                int co = r % COUT; r /= COUT;
                int c8 = r % (CIN >> 3); int tap = r / (CIN >> 3);
                v = w[(co * CIN + c8 * 8 + cl) * K2 + tap];
            } else if (t == 1) {
                int co = i % COUT; int r = i / COUT;
                int kk = r % K2; int ci = r / K2;
                v = w[(co * CIN + ci) * K2 + kk];
            } else {
                int co = i % COUT; int r = i / COUT;
                int kk = r % K2; int ci = r / K2;
                v = w[(ci * COUT + co) * K2 + kk];
            }
            dst[i] = v;
        }
    }
}

// tc1 parity repack into mma layout per parity block (CIN=128 -> c8 0..15, 4 taps)
__global__ void wtrans_tc1(const float* __restrict__ w, float* __restrict__ wt)
{
    int i = blockIdx.x * 256 + threadIdx.x;
    if (i >= 131072) return;
    int cl = i & 7; int r = i >> 3;
    int co = r & 63; r >>= 6;
    int c8 = r & 15; r >>= 4;
    int t = r & 3; int p = r >> 2;
    int py = p >> 1, px = p & 1;
    int kyp = t >> 1, kxp = t & 1;
    int ky = py ? (2 - 2 * kyp) : (3 - 2 * kyp);
    int kx = px ? (2 - 2 * kxp) : (3 - 2 * kxp);
    int ci = c8 * 8 + cl;
    wt[i] = w[(ci * 64 + co) * 16 + ky * 4 + kx];
}

// ---------------- tensor-core implicit-GEMM conv (ldmatrix version) ----------------
// Block: 128 px (4 rows x 32 cols) x COUT; 8 warps = 4M x 2N; warp = 32px x COUT/2.
// sA: [pixel][8ci] rows (32B); sB: [tap][co][8ci] rows (32B). Both feed ldmatrix.x4.
template<int CIN, int COUT, int KS, int S, int TAPCH,
         bool RELU_IN, bool HAS_BIAS, bool RELU_OUT, bool ADD_RES>
__global__ __launch_bounds__(256, 2)
void conv_mma(const float* __restrict__ in, const float* __restrict__ wt,
              const float* __restrict__ bias, const float* __restrict__ res,
              float* __restrict__ out, int H, int W, int PY, int PX,
              int OHF, int OWF, int OY0, int OYS, int OX0, int OXS)
{
    constexpr int ITH = 3 * S + KS;
    constexpr int ITW = 31 * S + KS;
    constexpr int RAW = ITH * ITW;
    constexpr int NSUB = COUT / 16;
    constexpr int NTAPS = KS * KS;
    constexpr int NSTG = NTAPS / TAPCH;
    constexpr int CIN8 = CIN / 8;

    __shared__ __align__(16) float sA[RAW * 8];
    __shared__ __align__(16) float sB[TAPCH * COUT * 8];

    const int ty = blockIdx.x;
    const int n  = blockIdx.z;
    const int tid = threadIdx.x;
    const int lane = tid & 31, wid = tid >> 5;
    const int wm = wid & 3, wn = wid >> 2;

    float c[2][NSUB][4];
#pragma unroll
    for (int mt = 0; mt < 2; mt++)
#pragma unroll
        for (int ns = 0; ns < NSUB; ns++)
#pragma unroll
            for (int q = 0; q < 4; q++) c[mt][ns][q] = 0.f;

    const int oyb = ty * 4;
    const int iy0 = oyb * S - PY;
    const int ix0 = -PX;
    const float* inb = in + (long)n * H * W * CIN;

    const unsigned sAu = (unsigned)__cvta_generic_to_shared(sA);
    const unsigned sBu = (unsigned)__cvta_generic_to_shared(sB);
    const int lane15 = lane & 15, segA = lane >> 4;
    const int coOff = (lane & 7) + ((lane & 16) >> 1);   // +8 for lanes 16-31
    const int segB = (lane >> 3) & 1;

    for (int cc = 0; cc < CIN; cc += 8) {
        for (int st = 0; st < NSTG; st++) {
            if (st == 0) {
                for (int i = tid; i < RAW; i += 256) {
                    int iy = i / ITW, ix = i - iy * ITW;
                    int gy = iy0 + iy, gx = ix0 + ix;
                    float4 v0 = make_float4(0.f, 0.f, 0.f, 0.f), v1 = v0;
                    if ((unsigned)gy < (unsigned)H && (unsigned)gx < (unsigned)W) {
                        const float4* p = (const float4*)(inb + ((long)gy * W + gx) * CIN + cc);
                        v0 = p[0]; v1 = p[1];
                        if (RELU_IN) {
                            v0.x = fmaxf(v0.x, 0.f); v0.y = fmaxf(v0.y, 0.f);
                            v0.z = fmaxf(v0.z, 0.f); v0.w = fmaxf(v0.w, 0.f);
                            v1.x = fmaxf(v1.x, 0.f); v1.y = fmaxf(v1.y, 0.f);
                            v1.z = fmaxf(v1.z, 0.f); v1.w = fmaxf(v1.w, 0.f);
                        }
                        v0 = tf4(v0); v1 = tf4(v1);
                    }
                    ((float4*)sA)[i * 2] = v0;
                    ((float4*)sA)[i * 2 + 1] = v1;
                }
            }
            {
                const float* wsrc = wt + ((long)(st * TAPCH) * CIN8 + (cc >> 3)) * (COUT * 8);
                for (int i = tid * 4; i < TAPCH * COUT * 8; i += 1024) {
                    int t = i / (COUT * 8);
                    int r = i - t * (COUT * 8);
                    float4 v = *(const float4*)(wsrc + (long)t * CIN8 * (COUT * 8) + r);
                    *(float4*)(sB + i) = tf4(v);
                }
            }
            __syncthreads();
#pragma unroll
            for (int tl = 0; tl < TAPCH; tl++) {
                const int tap = st * TAPCH + tl;
                const int ky = tap / KS, kx = tap - ky * KS;
                const int arow = (wm * S + ky) * ITW + kx;
                unsigned a[2][4];
#pragma unroll
                for (int mt = 0; mt < 2; mt++) {
                    unsigned ad = sAu + (unsigned)((arow + (mt * 16 + lane15) * S) * 32 + segA * 16);
                    ldsm4(a[mt][0], a[mt][1], a[mt][2], a[mt][3], ad);
                }
                unsigned b[NSUB][2];
#pragma unroll
                for (int np = 0; np < NSUB / 2; np++) {
                    unsigned bd = sBu + (unsigned)((tl * COUT + wn * (COUT / 2) + np * 16 + coOff) * 32
                                                   + segB * 16);
                    ldsm4(b[2 * np][0], b[2 * np][1], b[2 * np + 1][0], b[2 * np + 1][1], bd);
                }
#pragma unroll
                for (int mt = 0; mt < 2; mt++)
#pragma unroll
                    for (int ns = 0; ns < NSUB; ns++)
                        mma8(c[mt][ns], a[mt], b[ns]);
            }
            __syncthreads();
        }
    }

    // epilogue
    const int oy = oyb + wm;
    const int gy = OY0 + oy * OYS;
    const long nb = ((long)n * OHF + gy) * OWF;
#pragma unroll
    for (int mt = 0; mt < 2; mt++) {
#pragma unroll
        for (int half = 0; half < 2; half++) {
            int ox = mt * 16 + (lane >> 2) + half * 8;
            int gx = OX0 + ox * OXS;
            long pxbase = (nb + gx) * COUT;
#pragma unroll
            for (int ns = 0; ns < NSUB; ns++) {
                int co = wn * (COUT / 2) + ns * 8 + 2 * (lane & 3);
                long idx = pxbase + co;
                float v0 = c[mt][ns][half * 2 + 0];
                float v1 = c[mt][ns][half * 2 + 1];
                if (HAS_BIAS) {
                    float2 bb = *(const float2*)(bias + co);
                    v0 += bb.x; v1 += bb.y;
                }
                if (ADD_RES) {
                    float2 rr = *(const float2*)(res + idx);
                    v0 += rr.x; v1 += rr.y;
                }
                if (RELU_OUT) { v0 = fmaxf(v0, 0.f); v1 = fmaxf(v1, 0.f); }
                *(float2*)(out + idx) = make_float2(v0, v1);
            }
        }
    }
}

// ---------------- enc1: NCHW in (3ch) -> NHWC out, FFMA ----------------
__global__ __launch_bounds__(256)
void enc1_k(const float* __restrict__ in, const float* __restrict__ wt,
            const float* __restrict__ bias, float* __restrict__ out)
{
    constexpr int ITH = 18, ITW = 34;
    __shared__ float sm[3 * ITH * ITW];
    const int tile = blockIdx.x;
    const int tx = tile & 3, ty = tile >> 2;
    const int n = blockIdx.z;
    const int tid = threadIdx.x;
    const int ocl = (tid & 15) << 2;
    const int pg = tid >> 4;
    const int r = pg >> 1, ch = pg & 1;

    float acc[4][8];
#pragma unroll
    for (int o = 0; o < 4; o++)
#pragma unroll
        for (int p = 0; p < 8; p++) acc[o][p] = 0.f;

    const int iy0 = ty * 16 - 1, ix0 = tx * 32 - 1;
    const float* inb = in + (long)n * 3 * 128 * 128;

    for (int i = tid; i < 3 * ITH * ITW; i += 256) {
        int ci = i / (ITH * ITW);
        int rem = i - ci * (ITH * ITW);
        int iy = rem / ITW, ix = rem - iy * ITW;
        int gy = iy0 + iy, gx = ix0 + ix;
        float v = 0.f;
        if ((unsigned)gy < 128u && (unsigned)gx < 128u)
            v = inb[ci * 16384 + gy * 128 + gx];
        sm[i] = v;
    }
    __syncthreads();
#pragma unroll
    for (int ci = 0; ci < 3; ci++) {
        const float* sp = sm + ci * ITH * ITW + (r * 2) * ITW + (ch * 16);
        const float* wp = wt + (ci * 16) * 64 + ocl;
#pragma unroll
        for (int ky = 0; ky < 4; ky++) {
#pragma unroll
            for (int kx = 0; kx < 4; kx++) {
                float4 w4 = *(const float4*)(wp + (ky * 4 + kx) * 64);
                const float* sr = sp + ky * ITW + kx;
#pragma unroll
                for (int px = 0; px < 8; px++) {
                    float xv = sr[px * 2];
                    acc[0][px] = fmaf(w4.x, xv, acc[0][px]);
                    acc[1][px] = fmaf(w4.y, xv, acc[1][px]);
                    acc[2][px] = fmaf(w4.z, xv, acc[2][px]);
                    acc[3][px] = fmaf(w4.w, xv, acc[3][px]);
                }
            }
        }
    }
    float4 b4 = *(const float4*)(bias + ocl);
    const int oy = ty * 8 + r;
    const int oxb = tx * 16 + ch * 8;
#pragma unroll
    for (int px = 0; px < 8; px++) {
        float4 v;
        v.x = fmaxf(acc[0][px] + b4.x, 0.f);
        v.y = fmaxf(acc[1][px] + b4.y, 0.f);
        v.z = fmaxf(acc[2][px] + b4.z, 0.f);
        v.w = fmaxf(acc[3][px] + b4.w, 0.f);
        *(float4*)(out + (((long)n * 64 + oy) * 64 + oxb + px) * 64 + ocl) = v;
    }
}

// ---------------- tc2: NHWC in -> NCHW out (3ch), FFMA, 4 px/thread ----------------
__global__ __launch_bounds__(256)
void convt_c3(const float* __restrict__ in, const float* __restrict__ wt,
              const float* __restrict__ bias, float* __restrict__ out)
{
    constexpr int PLN = 400;                 // 6*66 = 396, padded
    __shared__ float swt[3072];
    __shared__ float sin_[8 * PLN];          // planar [ci][iy*66+ix]
    const int ty = blockIdx.x;               // 0..15
    const int n = blockIdx.z;
    const int tid = threadIdx.x;
    for (int i = tid; i < 3072; i += 256) swt[i] = wt[i];

    const int r = tid >> 5, cth = tid & 31;
    const int oy = ty * 8 + r;
    const int iyb = ty * 4 - 1;
    const int pey = oy & 1, pex = cth & 1;
    float acc[4][3];
#pragma unroll
    for (int u = 0; u < 4; u++) { acc[u][0] = 0.f; acc[u][1] = 0.f; acc[u][2] = 0.f; }
    const float* inb = in + (long)n * 64 * 64 * 64;
    const int lxb = ((cth + 1) >> 1) + 1;    // lx for jx=0 at u=0

    for (int cc = 0; cc < 64; cc += 8) {
        __syncthreads();
        for (int i = tid; i < 6 * 66; i += 256) {
            int iy = i / 66, ix = i - iy * 66;
            int gy = iyb + iy, gx = ix - 1;
            float4 v0 = make_float4(0.f, 0.f, 0.f, 0.f), v1 = v0;
            if ((unsigned)gy < 64u && (unsigned)gx < 64u) {
                const float4* p = (const float4*)(inb + ((long)gy * 64 + gx) * 64 + cc);
                v0 = p[0]; v1 = p[1];
            }
            sin_[0 * PLN + i] = v0.x; sin_[1 * PLN + i] = v0.y;
            sin_[2 * PLN + i] = v0.z; sin_[3 * PLN + i] = v0.w;
            sin_[4 * PLN + i] = v1.x; sin_[5 * PLN + i] = v1.y;
            sin_[6 * PLN + i] = v1.z; sin_[7 * PLN + i] = v1.w;
        }
        __syncthreads();
#pragma unroll 1
        for (int ci = 0; ci < 8; ci++) {
            const float* pl = sin_ + ci * PLN;
#pragma unroll
            for (int jy = 0; jy < 2; jy++) {
                int ly = ((oy + 1) >> 1) - jy - iyb;
                int ky = (1 - pey) + 2 * jy;
                const float* row = pl + ly * 66;
#pragma unroll
                for (int jx = 0; jx < 2; jx++) {
                    int kx = (1 - pex) + 2 * jx;
                    const float* w = swt + ((cc + ci) * 16 + ky * 4 + kx) * 3;
                    float w0 = w[0], w1 = w[1], w2 = w[2];
                    int lx0 = lxb - jx;
#pragma unroll
                    for (int u = 0; u < 4; u++) {
                        float xv = row[lx0 + 16 * u];
                        acc[u][0] = fmaf(xv, w0, acc[u][0]);
                        acc[u][1] = fmaf(xv, w1, acc[u][1]);
                        acc[u][2] = fmaf(xv, w2, acc[u][2]);
                    }
                }
            }
        }
    }
    long base = (long)n * 3 * 16384 + oy * 128 + cth;
    float b0 = bias[0], b1 = bias[1], b2 = bias[2];
#pragma unroll
    for (int u = 0; u < 4; u++) {
        out[base + 32 * u]          = acc[u][0] + b0;
        out[base + 16384 + 32 * u]  = acc[u][1] + b1;
        out[base + 32768 + 32 * u]  = acc[u][2] + b2;
    }
}

// ---------------- VQ ----------------
__global__ void vq_init(const float* __restrict__ E)
{
    int k = blockIdx.x * 128 + threadIdx.x;
    if (k < 512) {
        float s = 0.f;
#pragma unroll
        for (int d = 0; d < 64; d++) { float e = E[k * 64 + d]; s = fmaf(e, e, s); }
        g_En[k] = s;
        g_cnt[k] = 0;
    }
    if (k == 0) g_sse = 0.f;
}

__global__ __launch_bounds__(256)
void vq_fused(const float* __restrict__ ze, const float* __restrict__ E,
              float* __restrict__ zq)
{
    __shared__ float se[64 * 64];
    __shared__ float sen[64];
    __shared__ int h[512];
    __shared__ float red[8];
    const int tid = threadIdx.x;
    for (int i = tid; i < 512; i += 256) h[i] = 0;
    const int p = blockIdx.x * 256 + tid;
    float z[64];
    const float4* zp4 = (const float4*)(ze + (long)p * 64);
#pragma unroll
    for (int q = 0; q < 16; q++) {
        float4 v = zp4[q];
        z[4 * q] = v.x; z[4 * q + 1] = v.y; z[4 * q + 2] = v.z; z[4 * q + 3] = v.w;
    }
    float best = FLT_MAX;
    int bi = 0;
    for (int c0 = 0; c0 < 512; c0 += 64) {
        __syncthreads();
        for (int i = tid; i < 4096; i += 256) se[i] = E[c0 * 64 + i];
        if (tid < 64) sen[tid] = g_En[c0 + tid];
        __syncthreads();
        for (int k = 0; k < 64; k++) {
            const float4* ep = (const float4*)(se + k * 64);
            float dot = 0.f;
#pragma unroll
            for (int q = 0; q < 16; q++) {
                float4 e4 = ep[q];
                dot = fmaf(z[4 * q + 0], e4.x, dot);
                dot = fmaf(z[4 * q + 1], e4.y, dot);
                dot = fmaf(z[4 * q + 2], e4.z, dot);
                dot = fmaf(z[4 * q + 3], e4.w, dot);
            }
            float dist = sen[k] - 2.f * dot;
            if (dist < best) { best = dist; bi = c0 + k; }
        }
    }
    atomicAdd(&h[bi], 1);
    const float4* ep4 = (const float4*)(E + (long)bi * 64);
    float4* qp4 = (float4*)(zq + (long)p * 64);
    float sse = 0.f;
#pragma unroll
    for (int q = 0; q < 16; q++) {
        float4 e4 = ep4[q];
        float d0 = e4.x - z[4 * q + 0];
        float d1 = e4.y - z[4 * q + 1];
        float d2 = e4.z - z[4 * q + 2];
        float d3 = e4.w - z[4 * q + 3];
        sse = fmaf(d0, d0, sse); sse = fmaf(d1, d1, sse);
        sse = fmaf(d2, d2, sse); sse = fmaf(d3, d3, sse);
        qp4[q] = e4;
    }
#pragma unroll
    for (int off = 16; off; off >>= 1) sse += __shfl_down_sync(0xffffffffu, sse, off);
    if ((tid & 31) == 0) red[tid >> 5] = sse;
    __syncthreads();
    for (int i = tid; i < 512; i += 256)
        if (h[i]) atomicAdd(&g_cnt[i], h[i]);
    if (tid == 0) {
        float t = 0.f;
#pragma unroll
        for (int w = 0; w < 8; w++) t += red[w];
        atomicAdd(&g_sse, t);
    }
}

__global__ void finalize(float* __restrict__ out)
{
    __shared__ float red[512];
    int t = threadIdx.x;
    float cnt = (float)g_cnt[t];
    float pr = cnt * (1.f / 65536.f);
    red[t] = (cnt > 0.f) ? (-pr * log2f(pr + 1e-10f)) : 0.f;
    __syncthreads();
    for (int o = 256; o; o >>= 1) {
        if (t < o) red[t] += red[t + o];
        __syncthreads();
    }
    if (t == 0) {
        float ent = red[0];
        float mse = g_sse / (65536.f * 64.f);
        out[0] = 1.25f * mse;
        out[1 + 3145728] = mse;
        out[2 + 3145728] = mse;
        out[3 + 3145728] = exp2f(ent);
    }
}

// ---------------- host ----------------
extern "C" void kernel_launch(void* const* d_in, const int* in_sizes, int n_in,
                              void* d_out, int out_size)
{
    (void)in_sizes; (void)n_in; (void)out_size;
    const float* x        = (const float*)d_in[0];
    const float* enc_w1   = (const float*)d_in[1];
    const float* enc_b1   = (const float*)d_in[2];
    const float* enc_w2   = (const float*)d_in[3];
    const float* enc_b2   = (const float*)d_in[4];
    const float* enc_w3   = (const float*)d_in[5];
    const float* enc_b3   = (const float*)d_in[6];
    const float* enc_w4   = (const float*)d_in[7];
    const float* enc_b4   = (const float*)d_in[8];
    const float* eres_w1  = (const float*)d_in[9];
    const float* eres_w2  = (const float*)d_in[10];
    const float* eadj_w   = (const float*)d_in[11];
    const float* eadj_b   = (const float*)d_in[12];
    const float* E        = (const float*)d_in[13];
    const float* dadj_w   = (const float*)d_in[14];
    const float* dadj_b   = (const float*)d_in[15];
    const float* dres_w1  = (const float*)d_in[16];
    const float* dres_w2  = (const float*)d_in[17];
    const float* tc1_w    = (const float*)d_in[18];
    const float* tc1_b    = (const float*)d_in[19];
    const float* tc2_w    = (const float*)d_in[20];
    const float* tc2_b    = (const float*)d_in[21];

    float *h1, *a, *bb, *m, *ze, *zq, *wt;
    cudaGetSymbolAddress((void**)&h1, g_h1);
    cudaGetSymbolAddress((void**)&a,  g_a);
    cudaGetSymbolAddress((void**)&bb, g_b);
    cudaGetSymbolAddress((void**)&m,  g_m);
    cudaGetSymbolAddress((void**)&ze, g_ze);
    cudaGetSymbolAddress((void**)&zq, g_zq);
    cudaGetSymbolAddress((void**)&wt, g_wt);

    WArgs wa;
    wa.s[0] = enc_w1;  wa.s[1] = enc_w2;  wa.s[2] = enc_w3;  wa.s[3] = enc_w4;
    wa.s[4] = eres_w1; wa.s[5] = eres_w2; wa.s[6] = eadj_w;  wa.s[7] = dadj_w;
    wa.s[8] = dres_w1; wa.s[9] = dres_w2; wa.s[10] = tc2_w;
    wtrans_all<<<256, 256>>>(wa, wt);
    wtrans_tc1<<<512, 256>>>(tc1_w, wt + OFF_TC1);
    vq_init<<<4, 128>>>(E);

    const dim3 G(8, 1, 64);
    // ---- encoder ----
    enc1_k<<<dim3(32, 1, 64), 256>>>(x, wt + OFF_ENC1, enc_b1, h1);
    conv_mma<64, 128, 4, 2, 4, false, true, true, false>
        <<<G, 256>>>(h1, wt + OFF_ENC2, enc_b2, nullptr, a, 64, 64, 1, 1, 32, 32, 0, 1, 0, 1);
    conv_mma<128, 128, 3, 1, 9, false, true, true, false>
        <<<G, 256>>>(a, wt + OFF_ENC3, enc_b3, nullptr, bb, 32, 32, 1, 1, 32, 32, 0, 1, 0, 1);
    conv_mma<128, 128, 3, 1, 9, false, true, false, false>
        <<<G, 256>>>(bb, wt + OFF_ENC4, enc_b4, nullptr, a, 32, 32, 1, 1, 32, 32, 0, 1, 0, 1);
    conv_mma<128, 64, 3, 1, 9, true, false, false, false>
        <<<G, 256>>>(a, wt + OFF_ERES1_0, nullptr, nullptr, m, 32, 32, 1, 1, 32, 32, 0, 1, 0, 1);
    conv_mma<64, 128, 1, 1, 1, true, false, false, true>
        <<<G, 256>>>(m, wt + OFF_ERES2_0, nullptr, a, a, 32, 32, 0, 0, 32, 32, 0, 1, 0, 1);
    conv_mma<128, 64, 3, 1, 9, true, false, false, false>
        <<<G, 256>>>(a, wt + OFF_ERES1_1, nullptr, nullptr, m, 32, 32, 1, 1, 32, 32, 0, 1, 0, 1);
    conv_mma<64, 128, 1, 1, 1, true, false, false, true>
        <<<G, 256>>>(m, wt + OFF_ERES2_1, nullptr, a, a, 32, 32, 0, 0, 32, 32, 0, 1, 0, 1);
    conv_mma<128, 64, 1, 1, 1, true, true, false, false>
        <<<G, 256>>>(a, wt + OFF_EADJ, eadj_b, nullptr, ze, 32, 32, 0, 0, 32, 32, 0, 1, 0, 1);

    // ---- VQ ----
    vq_fused<<<256, 256>>>(ze, E, zq);

    // ---- decoder ----
    conv_mma<64, 128, 3, 1, 9, false, true, false, false>
        <<<G, 256>>>(zq, wt + OFF_DADJ, dadj_b, nullptr, a, 32, 32, 1, 1, 32, 32, 0, 1, 0, 1);
    conv_mma<128, 64, 3, 1, 9, true, false, false, false>
        <<<G, 256>>>(a, wt + OFF_DRES1_0, nullptr, nullptr, m, 32, 32, 1, 1, 32, 32, 0, 1, 0, 1);
    conv_mma<64, 128, 1, 1, 1, true, false, false, true>
        <<<G, 256>>>(m, wt + OFF_DRES2_0, nullptr, a, a, 32, 32, 0, 0, 32, 32, 0, 1, 0, 1);
    conv_mma<128, 64, 3, 1, 9, true, false, false, false>
        <<<G, 256>>>(a, wt + OFF_DRES1_1, nullptr, nullptr, m, 32, 32, 1, 1, 32, 32, 0, 1, 0, 1);
    conv_mma<64, 128, 1, 1, 1, true, false, false, true>
        <<<G, 256>>>(m, wt + OFF_DRES2_1, nullptr, a, a, 32, 32, 0, 0, 32, 32, 0, 1, 0, 1);
    // tc1: 4 parity classes, each a 2x2 stride-1 conv over 32x32 -> interleaved 64x64
    for (int p = 0; p < 4; p++) {
        int py = p >> 1, px = p & 1;
        conv_mma<128, 64, 2, 1, 4, true, true, true, false>
            <<<G, 256>>>(a, wt + OFF_TC1 + p * 32768, tc1_b, nullptr, h1,
                         32, 32, py ? 0 : 1, px ? 0 : 1, 64, 64, py, 2, px, 2);
    }
    convt_c3<<<dim3(16, 1, 64), 256>>>(h1, wt + OFF_TC2, tc2_b, (float*)d_out + 1);

    finalize<<<1, 512>>>((float*)d_out);
}

// round 10
// speedup vs baseline: 2.7920x; 1.1756x over previous
#include <cuda_runtime.h>
#include <cuda_fp16.h>
#include <math.h>
#include <float.h>

// ---------------- scratch (device globals; no allocation allowed) ----------------
__device__ float g_h1[64 * 64 * 64 * 64];   // (64,64,64,64) NHWC
__device__ float g_a [64 * 32 * 32 * 128];  // (64,32,32,128) NHWC
__device__ float g_b [64 * 32 * 32 * 128];
__device__ float g_m [64 * 32 * 32 * 64];
__device__ float g_ze[64 * 32 * 32 * 64];   // flat (65536,64)
__device__ float g_zq[64 * 32 * 32 * 64];
__device__ __align__(16) float g_wt[604160];   // float weights (ffma + tf32 mma)
__device__ __align__(16) __half g_wh[368640];  // f16 mma weights (decoder)
__device__ float g_En[512];
__device__ int   g_cnt[512];
__device__ float g_sse;

// float-weight offsets
#define F_ENC1     0        // 3072 (ffma OIHW-derived)
#define F_TC2      3072     // 3072 (ffma IOHW-derived)
#define W_ENC2     6144     // 16*8*128*8  = 131072  (tf32 mma: [tap][ci8][co][8])
#define W_ENC3     137216   // 9*16*128*8  = 147456
#define W_ENC4     284672   // 147456
#define W_ERES1_0  432128   // 9*16*64*8   = 73728
#define W_ERES1_1  505856
#define W_ERES2_0  579584   // 1*8*128*8   = 8192
#define W_ERES2_1  587776
#define W_EADJ     595968   // 1*16*64*8   = 8192
// half-weight offsets
#define H_DADJ     0        // 9*4*128*16  = 73728  (f16 mma: [tap][ci16][co][16])
#define H_DRES1_0  73728    // 9*8*64*16   = 73728
#define H_DRES1_1  147456
#define H_DRES2_0  221184   // 1*4*128*16  = 8192
#define H_DRES2_1  229376
#define H_TC1      237568   // 4 * 4*8*64*16 = 131072

// ---------------- helpers ----------------
__device__ __forceinline__ float tf32r(float f) {
    unsigned u; asm("cvt.rna.tf32.f32 %0, %1;" : "=r"(u) : "f"(f));
    return __uint_as_float(u);
}
__device__ __forceinline__ float4 tf4(float4 v) {
    v.x = tf32r(v.x); v.y = tf32r(v.y); v.z = tf32r(v.z); v.w = tf32r(v.w);
    return v;
}
__device__ __forceinline__ float4 rl4(float4 v) {
    v.x = fmaxf(v.x, 0.f); v.y = fmaxf(v.y, 0.f);
    v.z = fmaxf(v.z, 0.f); v.w = fmaxf(v.w, 0.f);
    return v;
}
__device__ __forceinline__ unsigned h2pk(float lo, float hi) {
    unsigned u; asm("cvt.rn.f16x2.f32 %0, %1, %2;" : "=r"(u) : "f"(hi), "f"(lo));
    return u;
}
__device__ __forceinline__ uint4 pk8(float4 a, float4 b) {
    uint4 r;
    r.x = h2pk(a.x, a.y); r.y = h2pk(a.z, a.w);
    r.z = h2pk(b.x, b.y); r.w = h2pk(b.z, b.w);
    return r;
}
__device__ __forceinline__ void mma8(float* c, const unsigned* a, const unsigned* b) {
    asm volatile(
        "mma.sync.aligned.m16n8k8.row.col.f32.tf32.tf32.f32 "
        "{%0,%1,%2,%3},{%4,%5,%6,%7},{%8,%9},{%0,%1,%2,%3};"
        : "+f"(c[0]), "+f"(c[1]), "+f"(c[2]), "+f"(c[3])
        : "r"(a[0]), "r"(a[1]), "r"(a[2]), "r"(a[3]), "r"(b[0]), "r"(b[1]));
}
__device__ __forceinline__ void mma16(float* c, const unsigned* a, const unsigned* b) {
    asm volatile(
        "mma.sync.aligned.m16n8k16.row.col.f32.f16.f16.f32 "
        "{%0,%1,%2,%3},{%4,%5,%6,%7},{%8,%9},{%0,%1,%2,%3};"
        : "+f"(c[0]), "+f"(c[1]), "+f"(c[2]), "+f"(c[3])
        : "r"(a[0]), "r"(a[1]), "r"(a[2]), "r"(a[3]), "r"(b[0]), "r"(b[1]));
}
__device__ __forceinline__ void ldsm4(unsigned& r0, unsigned& r1, unsigned& r2, unsigned& r3,
                                      unsigned addr) {
    asm volatile("ldmatrix.sync.aligned.m8n8.x4.shared.b16 {%0,%1,%2,%3}, [%4];"
                 : "=r"(r0), "=r"(r1), "=r"(r2), "=r"(r3) : "r"(addr));
}

// ---------------- fused weight transforms ----------------
struct WArgs { const float* s[11]; };
// s: 0 enc_w1, 1 enc_w2, 2 enc_w3, 3 enc_w4, 4 eres_w1, 5 eres_w2, 6 eadj_w,
//    7 dadj_w, 8 dres_w1, 9 dres_w2, 10 tc2_w

__global__ void wtrans_all(WArgs A, float* __restrict__ wf, __half* __restrict__ wh)
{
    const int gs = gridDim.x * blockDim.x;
    const int g0 = blockIdx.x * blockDim.x + threadIdx.x;

    // --- encoder tf32-mma layers (float, [tap][c8][co][8]) ---
    {
        const short sidx[8] = {1,2,3,4,4,5,5,6};
        const int   soff[8] = {0,0,0,0,73728,0,8192,0};
        const short cin_[8] = {64,128,128,128,128,64,64,128};
        const short cout_[8]= {128,128,128,64,64,128,128,64};
        const short k2_[8]  = {16,9,9,9,9,1,1,1};
        const int   doff[8] = {W_ENC2,W_ENC3,W_ENC4,W_ERES1_0,W_ERES1_1,
                               W_ERES2_0,W_ERES2_1,W_EADJ};
#pragma unroll 1
        for (int l = 0; l < 8; l++) {
            const float* w = A.s[sidx[l]] + soff[l];
            float* dst = wf + doff[l];
            const int CIN = cin_[l], COUT = cout_[l], K2 = k2_[l];
            const int C8 = CIN >> 3;
            const int n = CIN * COUT * K2;
            for (int i = g0; i < n; i += gs) {
                int cl = i & 7; int r = i >> 3;
                int co = r % COUT; r /= COUT;
                int c8 = r % C8; int tap = r / C8;
                dst[i] = w[(co * CIN + c8 * 8 + cl) * K2 + tap];
            }
        }
    }
    // --- decoder f16-mma layers (half, [tap][c16][co][16]) ---
    {
        const short sidx[5] = {7,8,8,9,9};
        const int   soff[5] = {0,0,73728,0,8192};
        const short cin_[5] = {64,128,128,64,64};
        const short cout_[5]= {128,64,64,128,128};
        const short k2_[5]  = {9,9,9,1,1};
        const int   doff[5] = {H_DADJ,H_DRES1_0,H_DRES1_1,H_DRES2_0,H_DRES2_1};
#pragma unroll 1
        for (int l = 0; l < 5; l++) {
            const float* w = A.s[sidx[l]] + soff[l];
            __half* dst = wh + doff[l];
            const int CIN = cin_[l], COUT = cout_[l], K2 = k2_[l];
            const int C16 = CIN >> 4;
            const int n = CIN * COUT * K2;
            for (int i = g0; i < n; i += gs) {
                int cl = i & 15; int r = i >> 4;
                int co = r % COUT; r /= COUT;
                int c16 = r % C16; int tap = r / C16;
                dst[i] = __float2half_rn(w[(co * CIN + c16 * 16 + cl) * K2 + tap]);
            }
        }
    }
    // enc1 (OIHW): wf[(ci*16+kk)*64+co] = w[(co*3+ci)*16+kk]
    for (int i = g0; i < 3072; i += gs) {
        int co = i & 63; int r = i >> 6;
        int kk = r & 15; int ci = r >> 4;
        wf[F_ENC1 + i] = A.s[0][(co * 3 + ci) * 16 + kk];
    }
    // tc2 (IOHW): wf[(ci*16+kk)*3+co] = w[(ci*3+co)*16+kk]
    for (int i = g0; i < 3072; i += gs) {
        int co = i % 3; int r = i / 3;
        int kk = r & 15; int ci = r >> 4;
        wf[F_TC2 + i] = A.s[10][(ci * 3 + co) * 16 + kk];
    }
}

// tc1 parity repack (convT w (128,64,4,4)) -> half mma layout, 4 parity sets
__global__ void wtrans_tc1(const float* __restrict__ w, __half* __restrict__ wh)
{
    int i = blockIdx.x * 256 + threadIdx.x;
    if (i >= 131072) return;
    int cl = i & 15; int r = i >> 4;
    int co = r & 63; r >>= 6;
    int c16 = r & 7; r >>= 3;
    int t = r & 3; int p = r >> 2;
    int py = p >> 1, px = p & 1;
    int kyp = t >> 1, kxp = t & 1;
    int ky = py ? (2 - 2 * kyp) : (3 - 2 * kyp);
    int kx = px ? (2 - 2 * kxp) : (3 - 2 * kxp);
    int ci = c16 * 16 + cl;
    wh[i] = __float2half_rn(w[(ci * 64 + co) * 16 + ky * 4 + kx]);
}

// ---------------- tf32 implicit-GEMM conv (encoder; proven numerics) ----------------
template<int CIN, int COUT, int KS, int S, int TAPCH,
         bool RELU_IN, bool HAS_BIAS, bool RELU_OUT, bool ADD_RES>
__global__ __launch_bounds__(256, 2)
void conv_tf32(const float* __restrict__ in, const float* __restrict__ wt,
               const float* __restrict__ bias, const float* __restrict__ res,
               float* __restrict__ out, int H, int W, int PY, int PX,
               int OHF, int OWF, int OY0, int OYS, int OX0, int OXS)
{
    constexpr int ITH = 3 * S + KS;
    constexpr int ITW = 31 * S + KS;
    constexpr int RAW = ITH * ITW;
    constexpr int NSUB = COUT / 16;
    constexpr int NTAPS = KS * KS;
    constexpr int NSTG = NTAPS / TAPCH;
    constexpr int CIN8 = CIN / 8;

    __shared__ __align__(16) float sA[RAW * 8];
    __shared__ __align__(16) float sB[TAPCH * COUT * 8];

    const int ty = blockIdx.x;
    const int n  = blockIdx.z;
    const int tid = threadIdx.x;
    const int lane = tid & 31, wid = tid >> 5;
    const int wm = wid & 3, wn = wid >> 2;

    float c[2][NSUB][4];
#pragma unroll
    for (int mt = 0; mt < 2; mt++)
#pragma unroll
        for (int ns = 0; ns < NSUB; ns++)
#pragma unroll
            for (int q = 0; q < 4; q++) c[mt][ns][q] = 0.f;

    const int oyb = ty * 4;
    const int iy0 = oyb * S - PY;
    const int ix0 = -PX;
    const float* inb = in + (long)n * H * W * CIN;

    const unsigned sAu = (unsigned)__cvta_generic_to_shared(sA);
    const unsigned sBu = (unsigned)__cvta_generic_to_shared(sB);
    const int lane15 = lane & 15, segA = lane >> 4;
    const int coOff = (lane & 7) + ((lane & 16) >> 1);
    const int segB = (lane >> 3) & 1;

    for (int cc = 0; cc < CIN; cc += 8) {
        for (int st = 0; st < NSTG; st++) {
            if (st == 0) {
                for (int i = tid; i < RAW; i += 256) {
                    int iy = i / ITW, ix = i - iy * ITW;
                    int gy = iy0 + iy, gx = ix0 + ix;
                    float4 v0 = make_float4(0.f, 0.f, 0.f, 0.f), v1 = v0;
                    if ((unsigned)gy < (unsigned)H && (unsigned)gx < (unsigned)W) {
                        const float4* p = (const float4*)(inb + ((long)gy * W + gx) * CIN + cc);
                        v0 = p[0]; v1 = p[1];
                        if (RELU_IN) { v0 = rl4(v0); v1 = rl4(v1); }
                        v0 = tf4(v0); v1 = tf4(v1);
                    }
                    ((float4*)sA)[i * 2] = v0;
                    ((float4*)sA)[i * 2 + 1] = v1;
                }
            }
            {
                const float* wsrc = wt + ((long)(st * TAPCH) * CIN8 + (cc >> 3)) * (COUT * 8);
                for (int i = tid * 4; i < TAPCH * COUT * 8; i += 1024) {
                    int t = i / (COUT * 8);
                    int r = i - t * (COUT * 8);
                    float4 v = *(const float4*)(wsrc + (long)t * CIN8 * (COUT * 8) + r);
                    *(float4*)(sB + i) = tf4(v);
                }
            }
            __syncthreads();
#pragma unroll
            for (int tl = 0; tl < TAPCH; tl++) {
                const int tap = st * TAPCH + tl;
                const int ky = tap / KS, kx = tap - ky * KS;
                const int arow = (wm * S + ky) * ITW + kx;
                unsigned a[2][4];
#pragma unroll
                for (int mt = 0; mt < 2; mt++) {
                    unsigned ad = sAu + (unsigned)((arow + (mt * 16 + lane15) * S) * 32 + segA * 16);
                    ldsm4(a[mt][0], a[mt][1], a[mt][2], a[mt][3], ad);
                }
                unsigned b[NSUB][2];
#pragma unroll
                for (int np = 0; np < NSUB / 2; np++) {
                    unsigned bd = sBu + (unsigned)((tl * COUT + wn * (COUT / 2) + np * 16 + coOff) * 32
                                                   + segB * 16);
                    ldsm4(b[2 * np][0], b[2 * np][1], b[2 * np + 1][0], b[2 * np + 1][1], bd);
                }
#pragma unroll
                for (int mt = 0; mt < 2; mt++)
#pragma unroll
                    for (int ns = 0; ns < NSUB; ns++)
                        mma8(c[mt][ns], a[mt], b[ns]);
            }
            __syncthreads();
        }
    }

    const int oy = oyb + wm;
    const int gy = OY0 + oy * OYS;
    const long nb = ((long)n * OHF + gy) * OWF;
#pragma unroll
    for (int mt = 0; mt < 2; mt++) {
#pragma unroll
        for (int half = 0; half < 2; half++) {
            int ox = mt * 16 + (lane >> 2) + half * 8;
            int gx = OX0 + ox * OXS;
            long pxbase = (nb + gx) * COUT;
#pragma unroll
            for (int ns = 0; ns < NSUB; ns++) {
                int co = wn * (COUT / 2) + ns * 8 + 2 * (lane & 3);
                long idx = pxbase + co;
                float v0 = c[mt][ns][half * 2 + 0];
                float v1 = c[mt][ns][half * 2 + 1];
                if (HAS_BIAS) {
                    float2 bb = *(const float2*)(bias + co);
                    v0 += bb.x; v1 += bb.y;
                }
                if (ADD_RES) {
                    float2 rr = *(const float2*)(res + idx);
                    v0 += rr.x; v1 += rr.y;
                }
                if (RELU_OUT) { v0 = fmaxf(v0, 0.f); v1 = fmaxf(v1, 0.f); }
                *(float2*)(out + idx) = make_float2(v0, v1);
            }
        }
    }
}

// ---------------- f16 implicit-GEMM conv (decoder; 2x MMA throughput) ----------------
template<int CIN, int COUT, int KS, int S, int TAPCH,
         bool RELU_IN, bool HAS_BIAS, bool RELU_OUT, bool ADD_RES>
__global__ __launch_bounds__(256, 2)
void conv_f16(const float* __restrict__ in, const __half* __restrict__ wt,
              const float* __restrict__ bias, const float* __restrict__ res,
              float* __restrict__ out, int H, int W, int PY, int PX,
              int OHF, int OWF, int OY0, int OYS, int OX0, int OXS)
{
    constexpr int ITH = 3 * S + KS;
    constexpr int ITW = 31 * S + KS;
    constexpr int RAW = ITH * ITW;
    constexpr int NSUB = COUT / 16;
    constexpr int NTAPS = KS * KS;
    constexpr int NSTG = NTAPS / TAPCH;
    constexpr int C16 = CIN / 16;

    __shared__ __align__(16) __half sA[RAW * 16];
    __shared__ __align__(16) __half sB[TAPCH * COUT * 16];

    const int ty = blockIdx.x;
    const int n  = blockIdx.z;
    const int tid = threadIdx.x;
    const int lane = tid & 31, wid = tid >> 5;
    const int wm = wid & 3, wn = wid >> 2;

    float c[2][NSUB][4];
#pragma unroll
    for (int mt = 0; mt < 2; mt++)
#pragma unroll
        for (int ns = 0; ns < NSUB; ns++)
#pragma unroll
            for (int q = 0; q < 4; q++) c[mt][ns][q] = 0.f;

    const int oyb = ty * 4;
    const int iy0 = oyb * S - PY;
    const int ix0 = -PX;
    const float* inb = in + (long)n * H * W * CIN;

    const unsigned sAu = (unsigned)__cvta_generic_to_shared(sA);
    const unsigned sBu = (unsigned)__cvta_generic_to_shared(sB);
    const int lane15 = lane & 15, segA = lane >> 4;
    const int coOff = (lane & 7) + ((lane & 16) >> 1);
    const int segB = (lane >> 3) & 1;

    for (int cc = 0; cc < C16; cc++) {
        for (int st = 0; st < NSTG; st++) {
            if (st == 0) {
                for (int i = tid; i < RAW; i += 256) {
                    int iy = i / ITW, ix = i - iy * ITW;
                    int gy = iy0 + iy, gx = ix0 + ix;
                    uint4 h0 = make_uint4(0, 0, 0, 0), h1 = h0;
                    if ((unsigned)gy < (unsigned)H && (unsigned)gx < (unsigned)W) {
                        const float4* p = (const float4*)(inb + ((long)gy * W + gx) * CIN + cc * 16);
                        float4 v0 = p[0], v1 = p[1], v2 = p[2], v3 = p[3];
                        if (RELU_IN) { v0 = rl4(v0); v1 = rl4(v1); v2 = rl4(v2); v3 = rl4(v3); }
                        h0 = pk8(v0, v1);
                        h1 = pk8(v2, v3);
                    }
                    ((uint4*)sA)[i * 2] = h0;
                    ((uint4*)sA)[i * 2 + 1] = h1;
                }
            }
            {
                const __half* wsrc = wt + ((long)(st * TAPCH) * C16 + cc) * (COUT * 16);
                for (int i = tid * 8; i < TAPCH * COUT * 16; i += 2048) {
                    int t = i / (COUT * 16);
                    int r = i - t * (COUT * 16);
                    *(uint4*)(sB + i) = *(const uint4*)(wsrc + (long)t * C16 * (COUT * 16) + r);
                }
            }
            __syncthreads();
#pragma unroll
            for (int tl = 0; tl < TAPCH; tl++) {
                const int tap = st * TAPCH + tl;
                const int ky = tap / KS, kx = tap - ky * KS;
                const int arow = (wm * S + ky) * ITW + kx;
                unsigned a[2][4];
#pragma unroll
                for (int mt = 0; mt < 2; mt++) {
                    unsigned ad = sAu + (unsigned)((arow + (mt * 16 + lane15) * S) * 32 + segA * 16);
                    ldsm4(a[mt][0], a[mt][1], a[mt][2], a[mt][3], ad);
                }
                unsigned b[NSUB][2];
#pragma unroll
                for (int np = 0; np < NSUB / 2; np++) {
                    unsigned bd = sBu + (unsigned)((tl * COUT + wn * (COUT / 2) + np * 16 + coOff) * 32
                                                   + segB * 16);
                    ldsm4(b[2 * np][0], b[2 * np][1], b[2 * np + 1][0], b[2 * np + 1][1], bd);
                }
#pragma unroll
                for (int mt = 0; mt < 2; mt++)
#pragma unroll
                    for (int ns = 0; ns < NSUB; ns++)
                        mma16(c[mt][ns], a[mt], b[ns]);
            }
            __syncthreads();
        }
    }

    const int oy = oyb + wm;
    const int gy = OY0 + oy * OYS;
    const long nb = ((long)n * OHF + gy) * OWF;
#pragma unroll
    for (int mt = 0; mt < 2; mt++) {
#pragma unroll
        for (int half = 0; half < 2; half++) {
            int ox = mt * 16 + (lane >> 2) + half * 8;
            int gx = OX0 + ox * OXS;
            long pxbase = (nb + gx) * COUT;
#pragma unroll
            for (int ns = 0; ns < NSUB; ns++) {
                int co = wn * (COUT / 2) + ns * 8 + 2 * (lane & 3);
                long idx = pxbase + co;
                float v0 = c[mt][ns][half * 2 + 0];
                float v1 = c[mt][ns][half * 2 + 1];
                if (HAS_BIAS) {
                    float2 bb = *(const float2*)(bias + co);
                    v0 += bb.x; v1 += bb.y;
                }
                if (ADD_RES) {
                    float2 rr = *(const float2*)(res + idx);
                    v0 += rr.x; v1 += rr.y;
                }
                if (RELU_OUT) { v0 = fmaxf(v0, 0.f); v1 = fmaxf(v1, 0.f); }
                *(float2*)(out + idx) = make_float2(v0, v1);
            }
        }
    }
}

// ---------------- enc1: NCHW in (3ch) -> NHWC out, FFMA ----------------
__global__ __launch_bounds__(256)
void enc1_k(const float* __restrict__ in, const float* __restrict__ wt,
            const float* __restrict__ bias, float* __restrict__ out)
{
    constexpr int ITH = 18, ITW = 34;
    __shared__ float sm[3 * ITH * ITW];
    const int tile = blockIdx.x;
    const int tx = tile & 3, ty = tile >> 2;
    const int n = blockIdx.z;
    const int tid = threadIdx.x;
    const int ocl = (tid & 15) << 2;
    const int pg = tid >> 4;
    const int r = pg >> 1, ch = pg & 1;

    float acc[4][8];
#pragma unroll
    for (int o = 0; o < 4; o++)
#pragma unroll
        for (int p = 0; p < 8; p++) acc[o][p] = 0.f;

    const int iy0 = ty * 16 - 1, ix0 = tx * 32 - 1;
    const float* inb = in + (long)n * 3 * 128 * 128;

    for (int i = tid; i < 3 * ITH * ITW; i += 256) {
        int ci = i / (ITH * ITW);
        int rem = i - ci * (ITH * ITW);
        int iy = rem / ITW, ix = rem - iy * ITW;
        int gy = iy0 + iy, gx = ix0 + ix;
        float v = 0.f;
        if ((unsigned)gy < 128u && (unsigned)gx < 128u)
            v = inb[ci * 16384 + gy * 128 + gx];
        sm[i] = v;
    }
    __syncthreads();
#pragma unroll
    for (int ci = 0; ci < 3; ci++) {
        const float* sp = sm + ci * ITH * ITW + (r * 2) * ITW + (ch * 16);
        const float* wp = wt + (ci * 16) * 64 + ocl;
#pragma unroll
        for (int ky = 0; ky < 4; ky++) {
#pragma unroll
            for (int kx = 0; kx < 4; kx++) {
                float4 w4 = *(const float4*)(wp + (ky * 4 + kx) * 64);
                const float* sr = sp + ky * ITW + kx;
#pragma unroll
                for (int px = 0; px < 8; px++) {
                    float xv = sr[px * 2];
                    acc[0][px] = fmaf(w4.x, xv, acc[0][px]);
                    acc[1][px] = fmaf(w4.y, xv, acc[1][px]);
                    acc[2][px] = fmaf(w4.z, xv, acc[2][px]);
                    acc[3][px] = fmaf(w4.w, xv, acc[3][px]);
                }
            }
        }
    }
    float4 b4 = *(const float4*)(bias + ocl);
    const int oy = ty * 8 + r;
    const int oxb = tx * 16 + ch * 8;
#pragma unroll
    for (int px = 0; px < 8; px++) {
        float4 v;
        v.x = fmaxf(acc[0][px] + b4.x, 0.f);
        v.y = fmaxf(acc[1][px] + b4.y, 0.f);
        v.z = fmaxf(acc[2][px] + b4.z, 0.f);
        v.w = fmaxf(acc[3][px] + b4.w, 0.f);
        *(float4*)(out + (((long)n * 64 + oy) * 64 + oxb + px) * 64 + ocl) = v;
    }
}

// ---------------- tc2: NHWC in -> NCHW out (3ch), FFMA, 4 px/thread ----------------
__global__ __launch_bounds__(256)
void convt_c3(const float* __restrict__ in, const float* __restrict__ wt,
              const float* __restrict__ bias, float* __restrict__ out)
{
    constexpr int PLN = 400;
    __shared__ float swt[3072];
    __shared__ float sin_[8 * PLN];
    const int ty = blockIdx.x;
    const int n = blockIdx.z;
    const int tid = threadIdx.x;
    for (int i = tid; i < 3072; i += 256) swt[i] = wt[i];

    const int r = tid >> 5, cth = tid & 31;
    const int oy = ty * 8 + r;
    const int iyb = ty * 4 - 1;
    const int pey = oy & 1, pex = cth & 1;
    float acc[4][3];
#pragma unroll
    for (int u = 0; u < 4; u++) { acc[u][0] = 0.f; acc[u][1] = 0.f; acc[u][2] = 0.f; }
    const float* inb = in + (long)n * 64 * 64 * 64;
    const int lxb = ((cth + 1) >> 1) + 1;

    for (int cc = 0; cc < 64; cc += 8) {
        __syncthreads();
        for (int i = tid; i < 6 * 66; i += 256) {
            int iy = i / 66, ix = i - iy * 66;
            int gy = iyb + iy, gx = ix - 1;
            float4 v0 = make_float4(0.f, 0.f, 0.f, 0.f), v1 = v0;
            if ((unsigned)gy < 64u && (unsigned)gx < 64u) {
                const float4* p = (const float4*)(inb + ((long)gy * 64 + gx) * 64 + cc);
                v0 = p[0]; v1 = p[1];
            }
            sin_[0 * PLN + i] = v0.x; sin_[1 * PLN + i] = v0.y;
            sin_[2 * PLN + i] = v0.z; sin_[3 * PLN + i] = v0.w;
            sin_[4 * PLN + i] = v1.x; sin_[5 * PLN + i] = v1.y;
            sin_[6 * PLN + i] = v1.z; sin_[7 * PLN + i] = v1.w;
        }
        __syncthreads();
#pragma unroll 1
        for (int ci = 0; ci < 8; ci++) {
            const float* pl = sin_ + ci * PLN;
#pragma unroll
            for (int jy = 0; jy < 2; jy++) {
                int ly = ((oy + 1) >> 1) - jy - iyb;
                int ky = (1 - pey) + 2 * jy;
                const float* row = pl + ly * 66;
#pragma unroll
                for (int jx = 0; jx < 2; jx++) {
                    int kx = (1 - pex) + 2 * jx;
                    const float* w = swt + ((cc + ci) * 16 + ky * 4 + kx) * 3;
                    float w0 = w[0], w1 = w[1], w2 = w[2];
                    int lx0 = lxb - jx;
#pragma unroll
                    for (int u = 0; u < 4; u++) {
                        float xv = row[lx0 + 16 * u];
                        acc[u][0] = fmaf(xv, w0, acc[u][0]);
                        acc[u][1] = fmaf(xv, w1, acc[u][1]);
                        acc[u][2] = fmaf(xv, w2, acc[u][2]);
                    }
                }
            }
        }
    }
    long base = (long)n * 3 * 16384 + oy * 128 + cth;
    float b0 = bias[0], b1 = bias[1], b2 = bias[2];
#pragma unroll
    for (int u = 0; u < 4; u++) {
        out[base + 32 * u]          = acc[u][0] + b0;
        out[base + 16384 + 32 * u]  = acc[u][1] + b1;
        out[base + 32768 + 32 * u]  = acc[u][2] + b2;
    }
}

// ---------------- VQ ----------------
__global__ void vq_init(const float* __restrict__ E)
{
    int k = blockIdx.x * 128 + threadIdx.x;
    if (k < 512) {
        float s = 0.f;
#pragma unroll
        for (int d = 0; d < 64; d++) { float e = E[k * 64 + d]; s = fmaf(e, e, s); }
        g_En[k] = s;
        g_cnt[k] = 0;
    }
    if (k == 0) g_sse = 0.f;
}

__global__ __launch_bounds__(256)
void vq_fused(const float* __restrict__ ze, const float* __restrict__ E,
              float* __restrict__ zq)
{
    __shared__ float se[64 * 64];
    __shared__ float sen[64];
    __shared__ int h[512];
    __shared__ float red[8];
    const int tid = threadIdx.x;
    for (int i = tid; i < 512; i += 256) h[i] = 0;
    const int p = blockIdx.x * 256 + tid;
    float z[64];
    const float4* zp4 = (const float4*)(ze + (long)p * 64);
#pragma unroll
    for (int q = 0; q < 16; q++) {
        float4 v = zp4[q];
        z[4 * q] = v.x; z[4 * q + 1] = v.y; z[4 * q + 2] = v.z; z[4 * q + 3] = v.w;
    }
    float best = FLT_MAX;
    int bi = 0;
    for (int c0 = 0; c0 < 512; c0 += 64) {
        __syncthreads();
        for (int i = tid; i < 4096; i += 256) se[i] = E[c0 * 64 + i];
        if (tid < 64) sen[tid] = g_En[c0 + tid];
        __syncthreads();
        for (int k = 0; k < 64; k++) {
            const float4* ep = (const float4*)(se + k * 64);
            float dot = 0.f;
#pragma unroll
            for (int q = 0; q < 16; q++) {
                float4 e4 = ep[q];
                dot = fmaf(z[4 * q + 0], e4.x, dot);
                dot = fmaf(z[4 * q + 1], e4.y, dot);
                dot = fmaf(z[4 * q + 2], e4.z, dot);
                dot = fmaf(z[4 * q + 3], e4.w, dot);
            }
            float dist = sen[k] - 2.f * dot;
            if (dist < best) { best = dist; bi = c0 + k; }
        }
    }
    atomicAdd(&h[bi], 1);
    const float4* ep4 = (const float4*)(E + (long)bi * 64);
    float4* qp4 = (float4*)(zq + (long)p * 64);
    float sse = 0.f;
#pragma unroll
    for (int q = 0; q < 16; q++) {
        float4 e4 = ep4[q];
        float d0 = e4.x - z[4 * q + 0];
        float d1 = e4.y - z[4 * q + 1];
        float d2 = e4.z - z[4 * q + 2];
        float d3 = e4.w - z[4 * q + 3];
        sse = fmaf(d0, d0, sse); sse = fmaf(d1, d1, sse);
        sse = fmaf(d2, d2, sse); sse = fmaf(d3, d3, sse);
        qp4[q] = e4;
    }
#pragma unroll
    for (int off = 16; off; off >>= 1) sse += __shfl_down_sync(0xffffffffu, sse, off);
    if ((tid & 31) == 0) red[tid >> 5] = sse;
    __syncthreads();
    for (int i = tid; i < 512; i += 256)
        if (h[i]) atomicAdd(&g_cnt[i], h[i]);
    if (tid == 0) {
        float t = 0.f;
#pragma unroll
        for (int w = 0; w < 8; w++) t += red[w];
        atomicAdd(&g_sse, t);
    }
}

__global__ void finalize(float* __restrict__ out)
{
    __shared__ float red[512];
    int t = threadIdx.x;
    float cnt = (float)g_cnt[t];
    float pr = cnt * (1.f / 65536.f);
    red[t] = (cnt > 0.f) ? (-pr * log2f(pr + 1e-10f)) : 0.f;
    __syncthreads();
    for (int o = 256; o; o >>= 1) {
        if (t < o) red[t] += red[t + o];
        __syncthreads();
    }
    if (t == 0) {
        float ent = red[0];
        float mse = g_sse / (65536.f * 64.f);
        out[0] = 1.25f * mse;
        out[1 + 3145728] = mse;
        out[2 + 3145728] = mse;
        out[3 + 3145728] = exp2f(ent);
    }
}

// ---------------- host ----------------
extern "C" void kernel_launch(void* const* d_in, const int* in_sizes, int n_in,
                              void* d_out, int out_size)
{
    (void)in_sizes; (void)n_in; (void)out_size;
    const float* x        = (const float*)d_in[0];
    const float* enc_w1   = (const float*)d_in[1];
    const float* enc_b1   = (const float*)d_in[2];
    const float* enc_w2   = (const float*)d_in[3];
    const float* enc_b2   = (const float*)d_in[4];
    const float* enc_w3   = (const float*)d_in[5];
    const float* enc_b3   = (const float*)d_in[6];
    const float* enc_w4   = (const float*)d_in[7];
    const float* enc_b4   = (const float*)d_in[8];
    const float* eres_w1  = (const float*)d_in[9];
    const float* eres_w2  = (const float*)d_in[10];
    const float* eadj_w   = (const float*)d_in[11];
    const float* eadj_b   = (const float*)d_in[12];
    const float* E        = (const float*)d_in[13];
    const float* dadj_w   = (const float*)d_in[14];
    const float* dadj_b   = (const float*)d_in[15];
    const float* dres_w1  = (const float*)d_in[16];
    const float* dres_w2  = (const float*)d_in[17];
    const float* tc1_w    = (const float*)d_in[18];
    const float* tc1_b    = (const float*)d_in[19];
    const float* tc2_w    = (const float*)d_in[20];
    const float* tc2_b    = (const float*)d_in[21];

    float *h1, *a, *bb, *m, *ze, *zq, *wf;
    __half *wh;
    cudaGetSymbolAddress((void**)&h1, g_h1);
    cudaGetSymbolAddress((void**)&a,  g_a);
    cudaGetSymbolAddress((void**)&bb, g_b);
    cudaGetSymbolAddress((void**)&m,  g_m);
    cudaGetSymbolAddress((void**)&ze, g_ze);
    cudaGetSymbolAddress((void**)&zq, g_zq);
    cudaGetSymbolAddress((void**)&wf, g_wt);
    cudaGetSymbolAddress((void**)&wh, g_wh);

    WArgs wa;
    wa.s[0] = enc_w1;  wa.s[1] = enc_w2;  wa.s[2] = enc_w3;  wa.s[3] = enc_w4;
    wa.s[4] = eres_w1; wa.s[5] = eres_w2; wa.s[6] = eadj_w;  wa.s[7] = dadj_w;
    wa.s[8] = dres_w1; wa.s[9] = dres_w2; wa.s[10] = tc2_w;
    wtrans_all<<<256, 256>>>(wa, wf, wh);
    wtrans_tc1<<<512, 256>>>(tc1_w, wh + H_TC1);
    vq_init<<<4, 128>>>(E);

    const dim3 G(8, 1, 64);
    // ---- encoder (tf32: proven argmin-safe numerics) ----
    enc1_k<<<dim3(32, 1, 64), 256>>>(x, wf + F_ENC1, enc_b1, h1);
    conv_tf32<64, 128, 4, 2, 4, false, true, true, false>
        <<<G, 256>>>(h1, wf + W_ENC2, enc_b2, nullptr, a, 64, 64, 1, 1, 32, 32, 0, 1, 0, 1);
    conv_tf32<128, 128, 3, 1, 9, false, true, true, false>
        <<<G, 256>>>(a, wf + W_ENC3, enc_b3, nullptr, bb, 32, 32, 1, 1, 32, 32, 0, 1, 0, 1);
    conv_tf32<128, 128, 3, 1, 9, false, true, false, false>
        <<<G, 256>>>(bb, wf + W_ENC4, enc_b4, nullptr, a, 32, 32, 1, 1, 32, 32, 0, 1, 0, 1);
    conv_tf32<128, 64, 3, 1, 9, true, false, false, false>
        <<<G, 256>>>(a, wf + W_ERES1_0, nullptr, nullptr, m, 32, 32, 1, 1, 32, 32, 0, 1, 0, 1);
    conv_tf32<64, 128, 1, 1, 1, true, false, false, true>
        <<<G, 256>>>(m, wf + W_ERES2_0, nullptr, a, a, 32, 32, 0, 0, 32, 32, 0, 1, 0, 1);
    conv_tf32<128, 64, 3, 1, 9, true, false, false, false>
        <<<G, 256>>>(a, wf + W_ERES1_1, nullptr, nullptr, m, 32, 32, 1, 1, 32, 32, 0, 1, 0, 1);
    conv_tf32<64, 128, 1, 1, 1, true, false, false, true>
        <<<G, 256>>>(m, wf + W_ERES2_1, nullptr, a, a, 32, 32, 0, 0, 32, 32, 0, 1, 0, 1);
    conv_tf32<128, 64, 1, 1, 1, true, true, false, false>
        <<<G, 256>>>(a, wf + W_EADJ, eadj_b, nullptr, ze, 32, 32, 0, 0, 32, 32, 0, 1, 0, 1);

    // ---- VQ (exact fp32) ----
    vq_fused<<<256, 256>>>(ze, E, zq);

    // ---- decoder (f16: 2x MMA throughput; only affects x_recon) ----
    conv_f16<64, 128, 3, 1, 9, false, true, false, false>
        <<<G, 256>>>(zq, wh + H_DADJ, dadj_b, nullptr, a, 32, 32, 1, 1, 32, 32, 0, 1, 0, 1);
    conv_f16<128, 64, 3, 1, 9, true, false, false, false>
        <<<G, 256>>>(a, wh + H_DRES1_0, nullptr, nullptr, m, 32, 32, 1, 1, 32, 32, 0, 1, 0, 1);
    conv_f16<64, 128, 1, 1, 1, true, false, false, true>
        <<<G, 256>>>(m, wh + H_DRES2_0, nullptr, a, a, 32, 32, 0, 0, 32, 32, 0, 1, 0, 1);
    conv_f16<128, 64, 3, 1, 9, true, false, false, false>
        <<<G, 256>>>(a, wh + H_DRES1_1, nullptr, nullptr, m, 32, 32, 1, 1, 32, 32, 0, 1, 0, 1);
    conv_f16<64, 128, 1, 1, 1, true, false, false, true>
        <<<G, 256>>>(m, wh + H_DRES2_1, nullptr, a, a, 32, 32, 0, 0, 32, 32, 0, 1, 0, 1);
    // tc1: 4 parity classes, each a 2x2 stride-1 conv over 32x32 -> interleaved 64x64
    for (int p = 0; p < 4; p++) {
        int py = p >> 1, px = p & 1;
        conv_f16<128, 64, 2, 1, 4, true, true, true, false>
            <<<G, 256>>>(a, wh + H_TC1 + p * 32768, tc1_b, nullptr, h1,
                         32, 32, py ? 0 : 1, px ? 0 : 1, 64, 64, py, 2, px, 2);
    }
    convt_c3<<<dim3(16, 1, 64), 256>>>(h1, wf + F_TC2, tc2_b, (float*)d_out + 1);

    finalize<<<1, 512>>>((float*)d_out);
}